// round 14
// baseline (speedup 1.0000x reference)
#include <cuda_runtime.h>
#include <cuda_bf16.h>
#include <cstdint>

// Problem constants
#define B_   1024
#define T_   200
#define E_   100
#define H_   200
#define G3_  600      // 3*H
#define NITEMS 100000

#define KPAD 256             // K padded storage for output GEMM operands
#define NT3  391             // ceil(100000/256)
#define NPADW (NT3*256)      // 100096

#define GI_KP 112            // K pad for GI GEMM
#define GI_NP 640            // N pad for GI GEMM

// Scratch (device globals; allocation is forbidden)
__device__ float g_GI[(size_t)T_ * B_ * G3_]; // gi = x@Wi+bi  [t][b][600]

// bf16 hi/lo operands for the mma.sync output GEMM
__device__ __nv_bfloat16 g_w_hi[(size_t)KPAD * NPADW];  // [k][n]
__device__ __nv_bfloat16 g_w_lo[(size_t)KPAD * NPADW];
__device__ __nv_bfloat16 g_h_hi[B_ * KPAD];             // [m][k]
__device__ __nv_bfloat16 g_h_lo[B_ * KPAD];
// Wh pre-fragged for scan mma: [t][mt 40][ks 13][lane 32] uint4
__device__ uint4 g_whf_hi[(size_t)T_ * 40 * 13 * 32];
__device__ uint4 g_whf_lo[(size_t)T_ * 40 * 13 * 32];
// Wi linear bf16 hi/lo for GI GEMM: [t][112][640]
__device__ __nv_bfloat16 g_wi_hi[(size_t)T_ * GI_KP * GI_NP];
__device__ __nv_bfloat16 g_wi_lo[(size_t)T_ * GI_KP * GI_NP];

static __device__ __forceinline__ float tanh_fast(float x) {
    float y; asm("tanh.approx.f32 %0, %1;" : "=f"(y) : "f"(x)); return y;
}
static __device__ __forceinline__ float sig_fast(float x) {
    return fmaf(tanh_fast(0.5f * x), 0.5f, 0.5f);
}
static __device__ __forceinline__ uint32_t smem_u32(const void* p) {
    uint32_t a;
    asm("{ .reg .u64 t; cvta.to.shared.u64 t, %1; cvt.u32.u64 %0, t; }" : "=r"(a) : "l"(p));
    return a;
}

// ---------------- mma.sync helpers ----------------
static __device__ __forceinline__ void ldmA(uint32_t* r, uint32_t addr) {
    asm volatile("ldmatrix.sync.aligned.m8n8.x4.shared.b16 {%0,%1,%2,%3}, [%4];"
        : "=r"(r[0]), "=r"(r[1]), "=r"(r[2]), "=r"(r[3]) : "r"(addr));
}
static __device__ __forceinline__ void ldmBT(uint32_t* r, uint32_t addr) {
    asm volatile("ldmatrix.sync.aligned.m8n8.x4.trans.shared.b16 {%0,%1,%2,%3}, [%4];"
        : "=r"(r[0]), "=r"(r[1]), "=r"(r[2]), "=r"(r[3]) : "r"(addr));
}
static __device__ __forceinline__ void mma_bf16(float* c, const uint32_t* a, const uint32_t* b) {
    asm volatile("mma.sync.aligned.m16n8k16.row.col.f32.bf16.bf16.f32 "
        "{%0,%1,%2,%3}, {%4,%5,%6,%7}, {%8,%9}, {%0,%1,%2,%3};"
        : "+f"(c[0]), "+f"(c[1]), "+f"(c[2]), "+f"(c[3])
        : "r"(a[0]), "r"(a[1]), "r"(a[2]), "r"(a[3]), "r"(b[0]), "r"(b[1]));
}
static __device__ __forceinline__ void bf_split(float v, unsigned short& h, unsigned short& l) {
    __nv_bfloat16 hh = __float2bfloat16(v);
    h = __bfloat16_as_ushort(hh);
    l = __bfloat16_as_ushort(__float2bfloat16(v - __bfloat162float(hh)));
}
static __device__ __forceinline__ void pack_split2(float v0, float v1, uint32_t& hi2, uint32_t& lo2) {
    asm("cvt.rn.bf16x2.f32 %0, %1, %2;" : "=r"(hi2) : "f"(v1), "f"(v0));
    float h0 = __uint_as_float(hi2 << 16);
    float h1 = __uint_as_float((hi2 >> 16) << 16);
    asm("cvt.rn.bf16x2.f32 %0, %1, %2;" : "=r"(lo2) : "f"(v1 - h1), "f"(v0 - h0));
}
static __device__ __forceinline__ void cp16(uint32_t dst, const void* src) {
    asm volatile("cp.async.cg.shared.global [%0], [%1], 16;" :: "r"(dst), "l"(src) : "memory");
}

// ---------------------------------------------------------------------------
// Wi conversion: [200][100][600] fp32 -> linear [200][112][640] bf16 hi/lo
// ---------------------------------------------------------------------------
__global__ void k_cvt_wi(const float* __restrict__ Wi) {
    int idx = blockIdx.x * 256 + threadIdx.x;   // 200*112*80
    if (idx >= T_ * GI_KP * 80) return;
    int n8 = idx % 80;
    int k  = (idx / 80) % GI_KP;
    int t  = idx / (80 * GI_KP);
    int n  = n8 * 8;

    union { unsigned short u[8]; uint4 v; } ph, pl;
    #pragma unroll
    for (int j = 0; j < 8; ++j) {
        float v = (k < E_ && n + j < G3_) ? __ldg(Wi + ((size_t)t * E_ + k) * G3_ + n + j) : 0.f;
        bf_split(v, ph.u[j], pl.u[j]);
    }
    size_t dst = ((size_t)t * GI_KP + k) * GI_NP + n;
    *(uint4*)(g_wi_hi + dst) = ph.v;
    *(uint4*)(g_wi_lo + dst) = pl.v;
}

// ---------------------------------------------------------------------------
// K2 mma v3: grid (bt 8, t 200); per CTA M=128 x N=640 x K=112.
// ---------------------------------------------------------------------------
#define GIA_STR 120
#define GIB_STR 136
#define GI3_A_BYTES (128 * GIA_STR * 2)
#define GI3_B_SPLIT (GI_KP * GIB_STR * 2)
#define GI3_B_BUF   (2 * GI3_B_SPLIT)
#define GI3_SMEM    (2 * GI3_A_BYTES + 2 * GI3_B_BUF)   // 183296

__global__ void __launch_bounds__(512, 1)
k_gi_mma(const int* __restrict__ q, const int* __restrict__ f,
         const float* __restrict__ eq, const float* __restrict__ ef,
         const float* __restrict__ bi) {
    extern __shared__ char sm[];
    __nv_bfloat16* sAh = (__nv_bfloat16*)sm;
    __nv_bfloat16* sAl = (__nv_bfloat16*)(sm + GI3_A_BYTES);
    char* sB = sm + 2 * GI3_A_BYTES;
    __shared__ int sq[128], sf[128];
    __shared__ float sbi[608];

    const int tid  = threadIdx.x;
    const int wid  = tid >> 5, lane = tid & 31;
    const int bt   = blockIdx.x;
    const int t    = blockIdx.y;
    const int wm   = wid & 1;
    const int wn   = wid >> 1;
    const int b_base = bt * 128;

    const uint32_t sB32 = smem_u32(sB);
    auto fillB = [&](int c, int p) {
        size_t srcbase = (size_t)t * GI_KP * GI_NP + c * 128;
        uint32_t dstbase = sB32 + p * GI3_B_BUF;
        for (int i = tid; i < 3584; i += 512) {
            int split = i / 1792;
            int r = i - split * 1792;
            int k = r >> 4, j = r & 15;
            const __nv_bfloat16* src = (split ? g_wi_lo : g_wi_hi) + srcbase + (size_t)k * GI_NP + j * 8;
            uint32_t dst = dstbase + split * GI3_B_SPLIT + (k * GIB_STR + j * 8) * 2;
            cp16(dst, src);
        }
        asm volatile("cp.async.commit_group;" ::: "memory");
    };

    fillB(0, 0);

    if (tid < 128) {
        sq[tid] = __ldg(q + (b_base + tid) * T_ + t);
        sf[tid] = __ldg(f + (b_base + tid) * T_ + t);
    }
    for (int i = tid; i < G3_; i += 512)
        sbi[i] = __ldg(bi + t * G3_ + i);
    __syncthreads();

    for (int i = tid; i < 128 * 25; i += 512) {
        int m = i / 25, c4 = i - m * 25;
        int k0 = c4 * 4;
        float4 a = __ldg((const float4*)(eq + sq[m] * E_ + k0));
        float4 b = __ldg((const float4*)(ef + sf[m] * E_ + k0));
        float vv[4] = {a.x * b.x, a.y * b.y, a.z * b.z, a.w * b.w};
        union { unsigned short u[4]; uint2 v; } ph, pl;
        #pragma unroll
        for (int j = 0; j < 4; ++j) bf_split(vv[j], ph.u[j], pl.u[j]);
        *(uint2*)(sAh + m * GIA_STR + k0) = ph.v;
        *(uint2*)(sAl + m * GIA_STR + k0) = pl.v;
    }
    for (int i = tid; i < 128 * 6; i += 512) {
        int m = i / 6, kk = 100 + 2 * (i - m * 6);
        *(uint32_t*)(sAh + m * GIA_STR + kk) = 0;
        *(uint32_t*)(sAl + m * GIA_STR + kk) = 0;
    }

    const uint32_t sAh32 = smem_u32(sAh), sAl32 = smem_u32(sAl);

    for (int c = 0; c < 5; ++c) {
        if (c + 1 < 5) {
            fillB(c + 1, (c + 1) & 1);
            asm volatile("cp.async.wait_group 1;" ::: "memory");
        } else {
            asm volatile("cp.async.wait_group 0;" ::: "memory");
        }
        __syncthreads();

        const uint32_t bh32 = sB32 + (c & 1) * GI3_B_BUF;
        const uint32_t bl32 = bh32 + GI3_B_SPLIT;

        float acc[4][2][4];
        #pragma unroll
        for (int i = 0; i < 4; ++i)
            #pragma unroll
            for (int j = 0; j < 2; ++j)
                #pragma unroll
                for (int k = 0; k < 4; ++k) acc[i][j][k] = 0.f;

        #pragma unroll
        for (int ks = 0; ks < 7; ++ks) {
            uint32_t Ah[4][4], Al[4][4];
            #pragma unroll
            for (int fm = 0; fm < 4; ++fm) {
                uint32_t off = ((wm * 64 + fm * 16 + (lane & 15)) * GIA_STR
                                + ks * 16 + (lane >> 4) * 8) * 2;
                ldmA(Ah[fm], sAh32 + off);
                ldmA(Al[fm], sAl32 + off);
            }
            uint32_t Bh[2][2], Bl[2][2];
            {
                uint32_t off = ((ks * 16 + (lane & 15)) * GIB_STR
                                + wn * 16 + (lane >> 4) * 8) * 2;
                uint32_t r[4];
                ldmBT(r, bh32 + off);
                Bh[0][0] = r[0]; Bh[0][1] = r[1];
                Bh[1][0] = r[2]; Bh[1][1] = r[3];
                ldmBT(r, bl32 + off);
                Bl[0][0] = r[0]; Bl[0][1] = r[1];
                Bl[1][0] = r[2]; Bl[1][1] = r[3];
            }
            #pragma unroll
            for (int fm = 0; fm < 4; ++fm)
                #pragma unroll
                for (int fn = 0; fn < 2; ++fn) {
                    mma_bf16(acc[fm][fn], Ah[fm], Bh[fn]);
                    mma_bf16(acc[fm][fn], Ah[fm], Bl[fn]);
                    mma_bf16(acc[fm][fn], Al[fm], Bh[fn]);
                }
        }

        #pragma unroll
        for (int fm = 0; fm < 4; ++fm) {
            int gm = b_base + wm * 64 + fm * 16 + (lane >> 2);
            #pragma unroll
            for (int fn = 0; fn < 2; ++fn) {
                int gn = c * 128 + wn * 16 + fn * 8 + (lane & 3) * 2;
                if (gn < G3_) {
                    float2 bv = *(float2*)&sbi[gn];
                    float2 o0 = make_float2(acc[fm][fn][0] + bv.x, acc[fm][fn][1] + bv.y);
                    float2 o1 = make_float2(acc[fm][fn][2] + bv.x, acc[fm][fn][3] + bv.y);
                    *(float2*)(g_GI + ((size_t)t * B_ + gm) * G3_ + gn) = o0;
                    *(float2*)(g_GI + ((size_t)t * B_ + gm + 8) * G3_ + gn) = o1;
                }
            }
        }
        __syncthreads();
    }
}

// ---------------------------------------------------------------------------
// Wh -> fragment layout conversion (once).
// ---------------------------------------------------------------------------
__global__ void __launch_bounds__(128)
k_cvt_whf(const float* __restrict__ Wh) {
    __shared__ float sA[208][17];
    const int mt = blockIdx.x;   // 0..37
    const int t  = blockIdx.y;
    const int tid = threadIdx.x;
    const int m0 = mt * 16;

    for (int i = tid; i < 208 * 16; i += 128) {
        int k = i >> 4, mm = i & 15;
        int m = m0 + mm;
        float v = (k < H_ && m < G3_) ? __ldg(Wh + ((size_t)t * H_ + k) * G3_ + m) : 0.f;
        sA[k][mm] = v;
    }
    __syncthreads();

    const int wid = tid >> 5, lane = tid & 31;
    const int g = lane >> 2, c = lane & 3;
    for (int ks = wid; ks < 13; ks += 4) {
        int k0 = ks * 16 + 2 * c;
        uint4 uh, ul;
        pack_split2(sA[k0][g],       sA[k0 + 1][g],     uh.x, ul.x);
        pack_split2(sA[k0][g + 8],   sA[k0 + 1][g + 8], uh.y, ul.y);
        pack_split2(sA[k0 + 8][g],   sA[k0 + 9][g],     uh.z, ul.z);
        pack_split2(sA[k0 + 8][g+8], sA[k0 + 9][g + 8], uh.w, ul.w);
        size_t idx = (((size_t)t * 40 + mt) * 13 + ks) * 32 + lane;
        g_whf_hi[idx] = uh;
        g_whf_lo[idx] = ul;
    }
}

// ---------------------------------------------------------------------------
// K3: GRU scan v8. 128 CTAs x 8 rows, 608 threads.
// tanh.approx gates, single-pass float4 gate phase.
// ---------------------------------------------------------------------------
#define SOFF_GI   0                      // [8][600] f32    19200
#define SOFF_GH   19200                  // [608][10] f32   24320
#define SOFF_HF   43520                  // [8][200] f32    6400
#define SOFF_HHI  49920                  // [8][132] u32    4224
#define SOFF_HLO  54144                  //                 4224
#define SOFF_BHN  58368                  // [200] f32       800
#define SCAN_SMEM 59168

#define WHF_S1    (19 * 13 * 32)
#define WHF_TSTEP (40 * 13 * 32)

__global__ void __launch_bounds__(608, 1)
k_scan_mma(const float* __restrict__ bhn, const float* __restrict__ ic) {
    extern __shared__ char sm[];
    float*    sgi = (float*)(sm + SOFF_GI);
    float*    sgh = (float*)(sm + SOFF_GH);
    float*    shf = (float*)(sm + SOFF_HF);
    uint32_t* hh  = (uint32_t*)(sm + SOFF_HHI);
    uint32_t* hl  = (uint32_t*)(sm + SOFF_HLO);
    float*    sbh = (float*)(sm + SOFF_BHN);

    const int tid  = threadIdx.x;
    const int wid  = tid >> 5, lane = tid & 31;
    const int b0   = blockIdx.x * 8;
    const int g    = lane >> 2, cc = lane & 3;
    const uint32_t sgi_a = smem_u32(sgi);
    const uint32_t sbh_a = smem_u32(sbh);

    for (int i = tid; i < 8 * 132; i += 608) {
        int w = i % 132;
        uint32_t hi2 = 0, lo2 = 0;
        if (w < 100) {
            float v0 = __ldg(ic + 2 * w), v1 = __ldg(ic + 2 * w + 1);
            pack_split2(v0, v1, hi2, lo2);
        }
        hh[i] = hi2; hl[i] = lo2;
    }
    for (int i = tid; i < 1600; i += 608)
        shf[i] = __ldg(ic + (i % 200));
    __syncthreads();

    float acc0a[4], acc0b[4], acc1a[4], acc1b[4];
    uint4 bh0[2], bl0[2], bh1[2], bl1[2];

    const uint4* ph = g_whf_hi + ((size_t)wid * 13) * 32 + lane;
    const uint4* pl = g_whf_lo + ((size_t)wid * 13) * 32 + lane;

    bh0[0] = __ldg(ph);               bl0[0] = __ldg(pl);
    bh1[0] = __ldg(ph + WHF_S1);      bl1[0] = __ldg(pl + WHF_S1);
    bh0[1] = __ldg(ph + 32);          bl0[1] = __ldg(pl + 32);
    bh1[1] = __ldg(ph + WHF_S1 + 32); bl1[1] = __ldg(pl + WHF_S1 + 32);

    for (int t = 0; t < T_; ++t) {
        {
            const float* gib = g_GI + ((size_t)t * B_ + b0) * G3_;
            for (int i = tid; i < 1250; i += 608) {
                if (i < 1200) {
                    int b = i / 150, o = (i - b * 150) * 16;
                    cp16(sgi_a + b * 2400 + o, (const char*)(gib + b * G3_) + o);
                } else {
                    int j = i - 1200;
                    cp16(sbh_a + j * 16, (const char*)(bhn + t * H_) + j * 16);
                }
            }
            asm volatile("cp.async.commit_group;" ::: "memory");
        }

        #pragma unroll
        for (int c = 0; c < 4; ++c) { acc0a[c] = 0.f; acc0b[c] = 0.f; acc1a[c] = 0.f; acc1b[c] = 0.f; }

        #pragma unroll
        for (int ks = 0; ks < 13; ++ks) {
            const int p = ks & 1;
            uint4 a0h = bh0[p], a0l = bl0[p], a1h = bh1[p], a1l = bl1[p];
            if (ks + 2 < 13) {
                int off = (ks + 2) * 32;
                bh0[p] = __ldg(ph + off);          bl0[p] = __ldg(pl + off);
                bh1[p] = __ldg(ph + WHF_S1 + off); bl1[p] = __ldg(pl + WHF_S1 + off);
            }
            int r0 = g * 132 + ks * 8 + cc;
            uint32_t Bh[2] = { hh[r0], hh[r0 + 4] };
            uint32_t Bl[2] = { hl[r0], hl[r0 + 4] };
            uint32_t Ah0[4] = {a0h.x, a0h.y, a0h.z, a0h.w};
            uint32_t Al0[4] = {a0l.x, a0l.y, a0l.z, a0l.w};
            uint32_t Ah1[4] = {a1h.x, a1h.y, a1h.z, a1h.w};
            uint32_t Al1[4] = {a1l.x, a1l.y, a1l.z, a1l.w};
            mma_bf16(acc0a, Ah0, Bh);
            mma_bf16(acc1a, Ah1, Bh);
            mma_bf16(acc0b, Ah0, Bl);
            mma_bf16(acc1b, Ah1, Bl);
            mma_bf16(acc0b, Al0, Bh);
            mma_bf16(acc1b, Al1, Bh);
        }

        {
            int m0 = wid * 16;
            *(float2*)&sgh[(m0 + g) * 10 + cc * 2]     = make_float2(acc0a[0] + acc0b[0], acc0a[1] + acc0b[1]);
            *(float2*)&sgh[(m0 + g + 8) * 10 + cc * 2] = make_float2(acc0a[2] + acc0b[2], acc0a[3] + acc0b[3]);
            int m1 = (wid + 19) * 16;
            *(float2*)&sgh[(m1 + g) * 10 + cc * 2]     = make_float2(acc1a[0] + acc1b[0], acc1a[1] + acc1b[1]);
            *(float2*)&sgh[(m1 + g + 8) * 10 + cc * 2] = make_float2(acc1a[2] + acc1b[2], acc1a[3] + acc1b[3]);
        }

        if (t + 1 < T_) {
            ph += WHF_TSTEP;
            pl += WHF_TSTEP;
            bh0[0] = __ldg(ph);               bl0[0] = __ldg(pl);
            bh1[0] = __ldg(ph + WHF_S1);      bl1[0] = __ldg(pl + WHF_S1);
            bh0[1] = __ldg(ph + 32);          bl0[1] = __ldg(pl + 32);
            bh1[1] = __ldg(ph + WHF_S1 + 32); bl1[1] = __ldg(pl + WHF_S1 + 32);
        }

        asm volatile("cp.async.wait_group 0;" ::: "memory");
        __syncthreads();

        // gate phase: single pass, 400 float4 items (b, j quad)
        if (tid < 400) {
            int b = tid / 50, jq = tid - b * 50;
            int j = jq * 4;
            const float* gib = sgi + b * G3_;
            float4 gr = *(const float4*)(gib + j);
            float4 gz = *(const float4*)(gib + 200 + j);
            float4 gn = *(const float4*)(gib + 400 + j);
            float4 bv = *(const float4*)(sbh + j);
            float4 ho = *(const float4*)(shf + b * 200 + j);
            float hr[4], hz[4], hn_[4];
            #pragma unroll
            for (int d = 0; d < 4; ++d) {
                hr[d]  = sgh[(j + d) * 10 + b];
                hz[d]  = sgh[(200 + j + d) * 10 + b];
                hn_[d] = sgh[(400 + j + d) * 10 + b];
            }
            float grr[4] = {gr.x, gr.y, gr.z, gr.w};
            float gzz[4] = {gz.x, gz.y, gz.z, gz.w};
            float gnn[4] = {gn.x, gn.y, gn.z, gn.w};
            float bvv[4] = {bv.x, bv.y, bv.z, bv.w};
            float hoo[4] = {ho.x, ho.y, ho.z, ho.w};
            float hnew[4];
            #pragma unroll
            for (int d = 0; d < 4; ++d) {
                float r = sig_fast(grr[d] + hr[d]);
                float z = sig_fast(gzz[d] + hz[d]);
                float n = tanh_fast(gnn[d] + r * (hn_[d] + bvv[d]));
                hnew[d] = (1.f - z) * n + z * hoo[d];
            }
            *(float4*)(shf + b * 200 + j) = make_float4(hnew[0], hnew[1], hnew[2], hnew[3]);
            uint32_t hiA, loA, hiB, loB;
            pack_split2(hnew[0], hnew[1], hiA, loA);
            pack_split2(hnew[2], hnew[3], hiB, loB);
            int jp = j >> 1;
            *(uint2*)&hh[b * 132 + jp] = make_uint2(hiA, hiB);
            *(uint2*)&hl[b * 132 + jp] = make_uint2(loA, loB);
        }
        __syncthreads();
    }

    // final: fused bf16 hi/lo conversion of hT for the output GEMM
    for (int i = tid; i < 8 * 128; i += 608) {
        int b = i / 128, kp = i - b * 128;
        int k0 = kp * 2;
        float v0 = (k0 < H_) ? shf[b * 200 + k0] : 0.f;
        float v1 = (k0 + 1 < H_) ? shf[b * 200 + k0 + 1] : 0.f;
        uint32_t hi2, lo2;
        pack_split2(v0, v1, hi2, lo2);
        *(uint32_t*)(g_h_hi + (size_t)(b0 + b) * KPAD + k0) = hi2;
        *(uint32_t*)(g_h_lo + (size_t)(b0 + b) * KPAD + k0) = lo2;
    }
}

// ---------------------------------------------------------------------------
// Wout conversion
// ---------------------------------------------------------------------------
__global__ void k_cvt_w(const float* __restrict__ Wout) {
    int nb = blockIdx.x * 256 + threadIdx.x;
    int k  = blockIdx.y;
    if (nb >= NPADW / 8) return;
    int n = nb * 8;

    union { unsigned short u[8]; uint4 v; } ph, pl;
    if (k < H_ && n + 7 < NITEMS) {
        const float4* src = (const float4*)(Wout + (size_t)k * NITEMS + n);
        float4 v0 = __ldg(src), v1 = __ldg(src + 1);
        float vv[8] = {v0.x, v0.y, v0.z, v0.w, v1.x, v1.y, v1.z, v1.w};
        #pragma unroll
        for (int j = 0; j < 8; ++j) bf_split(vv[j], ph.u[j], pl.u[j]);
    } else {
        #pragma unroll
        for (int j = 0; j < 8; ++j) {
            float v = (k < H_ && n + j < NITEMS) ? __ldg(Wout + (size_t)k * NITEMS + n + j) : 0.f;
            bf_split(v, ph.u[j], pl.u[j]);
        }
    }
    *(uint4*)(g_w_hi + (size_t)k * NPADW + n) = ph.v;
    *(uint4*)(g_w_lo + (size_t)k * NPADW + n) = pl.v;
}

// ---------------------------------------------------------------------------
// K4 mma.sync v3: 512 threads, BN=256, K=208 (chunks 64/64/64/16), cp.async.
// ---------------------------------------------------------------------------
#define OASTR 72
#define OBSTR 264
#define OUT_AB (128 * OASTR * 2)
#define OUT_BB (64 * OBSTR * 2)
#define OUT_BUF (2 * OUT_AB + 2 * OUT_BB)
#define MMA_SMEM (2 * OUT_BUF)              // 208896

__global__ void __launch_bounds__(512, 1)
k_out_mma(const float* __restrict__ bout, float* __restrict__ out) {
    extern __shared__ char smc[];
    const int tid  = threadIdx.x;
    const int wid  = tid >> 5, lane = tid & 31;
    const int mt   = blockIdx.x;
    const int nt   = blockIdx.y;
    const int wm   = wid & 1;
    const int wn   = wid >> 1;
    const uint32_t sbase = smem_u32(smc);

    auto fill = [&](int kc, int p) {
        const int nk = (kc < 3) ? 4 : 1;
        const int k0 = kc * 64;
        uint32_t buf = sbase + p * OUT_BUF;
        int per = nk * 2;
        int aTot = 2 * 128 * per;
        for (int i = tid; i < aTot; i += 512) {
            int split = i / (128 * per);
            int r = i - split * 128 * per;
            int m = r / per, kb = r - m * per;
            const __nv_bfloat16* src = (split ? g_h_lo : g_h_hi)
                + (size_t)(mt * 128 + m) * KPAD + k0 + kb * 8;
            cp16(buf + split * OUT_AB + (m * OASTR + kb * 8) * 2, src);
        }
        int rows = nk * 16;
        int bTot = 2 * rows * 32;
        for (int i = tid; i < bTot; i += 512) {
            int split = i / (rows * 32);
            int r = i - split * rows * 32;
            int k = r >> 5, nb = r & 31;
            const __nv_bfloat16* src = (split ? g_w_lo : g_w_hi)
                + (size_t)(k0 + k) * NPADW + nt * 256 + nb * 8;
            cp16(buf + 2 * OUT_AB + split * OUT_BB + (k * OBSTR + nb * 8) * 2, src);
        }
        asm volatile("cp.async.commit_group;" ::: "memory");
    };

    fill(0, 0);

    float acc[4][4][4];
    #pragma unroll
    for (int i = 0; i < 4; ++i)
        #pragma unroll
        for (int j = 0; j < 4; ++j)
            #pragma unroll
            for (int c = 0; c < 4; ++c) acc[i][j][c] = 0.f;

    for (int kc = 0; kc < 4; ++kc) {
        if (kc + 1 < 4) {
            fill(kc + 1, (kc + 1) & 1);
            asm volatile("cp.async.wait_group 1;" ::: "memory");
        } else {
            asm volatile("cp.async.wait_group 0;" ::: "memory");
        }
        __syncthreads();

        uint32_t buf = sbase + (kc & 1) * OUT_BUF;
        const uint32_t sAh32 = buf, sAl32 = buf + OUT_AB;
        const uint32_t sBh32 = buf + 2 * OUT_AB, sBl32 = sBh32 + OUT_BB;
        const int nk = (kc < 3) ? 4 : 1;

        #pragma unroll 4
        for (int ks = 0; ks < nk; ++ks) {
            uint32_t Ah[4][4], Al[4][4];
            #pragma unroll
            for (int fm = 0; fm < 4; ++fm) {
                uint32_t off = ((wm * 64 + fm * 16 + (lane & 15)) * OASTR
                                + ks * 16 + (lane >> 4) * 8) * 2;
                ldmA(Ah[fm], sAh32 + off);
                ldmA(Al[fm], sAl32 + off);
            }
            uint32_t Bh[4][2], Bl[4][2];
            #pragma unroll
            for (int fb = 0; fb < 2; ++fb) {
                uint32_t off = ((ks * 16 + (lane & 15)) * OBSTR
                                + wn * 32 + fb * 16 + (lane >> 4) * 8) * 2;
                uint32_t r[4];
                ldmBT(r, sBh32 + off);
                Bh[fb*2][0] = r[0]; Bh[fb*2][1] = r[1];
                Bh[fb*2+1][0] = r[2]; Bh[fb*2+1][1] = r[3];
                ldmBT(r, sBl32 + off);
                Bl[fb*2][0] = r[0]; Bl[fb*2][1] = r[1];
                Bl[fb*2+1][0] = r[2]; Bl[fb*2+1][1] = r[3];
            }
            #pragma unroll
            for (int fm = 0; fm < 4; ++fm)
                #pragma unroll
                for (int fn = 0; fn < 4; ++fn) {
                    mma_bf16(acc[fm][fn], Ah[fm], Bh[fn]);
                    mma_bf16(acc[fm][fn], Ah[fm], Bl[fn]);
                    mma_bf16(acc[fm][fn], Al[fm], Bh[fn]);
                }
        }
        __syncthreads();
    }

    #pragma unroll
    for (int fm = 0; fm < 4; ++fm) {
        int gm = mt * 128 + wm * 64 + fm * 16 + (lane >> 2);
        #pragma unroll
        for (int fn = 0; fn < 4; ++fn) {
            int gn = nt * 256 + wn * 32 + fn * 8 + (lane & 3) * 2;
            if (gn < NITEMS) {
                float2 bv = __ldg((const float2*)(bout + gn));
                float2 o0 = make_float2(acc[fm][fn][0] + bv.x, acc[fm][fn][1] + bv.y);
                float2 o1 = make_float2(acc[fm][fn][2] + bv.x, acc[fm][fn][3] + bv.y);
                *(float2*)(out + (size_t)gm * NITEMS + gn) = o0;
                *(float2*)(out + (size_t)(gm + 8) * NITEMS + gn) = o1;
            }
        }
    }
}

// ---------------------------------------------------------------------------
extern "C" void kernel_launch(void* const* d_in, const int* in_sizes, int n_in,
                              void* d_out, int out_size) {
    const int*   q    = (const int*)  d_in[0];
    const int*   f    = (const int*)  d_in[1];
    const float* eq   = (const float*)d_in[2];
    const float* ef   = (const float*)d_in[3];
    const float* ic   = (const float*)d_in[4];
    const float* Wi   = (const float*)d_in[5];
    const float* bi   = (const float*)d_in[6];
    const float* Wh   = (const float*)d_in[7];
    const float* bhn  = (const float*)d_in[8];
    const float* Wout = (const float*)d_in[9];
    const float* bout = (const float*)d_in[10];
    float* out = (float*)d_out;

    static cudaStream_t s1 = nullptr, s2 = nullptr;
    static cudaEvent_t evFork = nullptr, evWhf = nullptr, evW = nullptr;
    static bool init_done = false;
    if (!init_done) {
        cudaFuncSetAttribute(k_gi_mma,   cudaFuncAttributeMaxDynamicSharedMemorySize, GI3_SMEM);
        cudaFuncSetAttribute(k_scan_mma, cudaFuncAttributeMaxDynamicSharedMemorySize, SCAN_SMEM);
        cudaFuncSetAttribute(k_out_mma,  cudaFuncAttributeMaxDynamicSharedMemorySize, MMA_SMEM);
        cudaStreamCreateWithFlags(&s1, cudaStreamNonBlocking);
        cudaStreamCreateWithFlags(&s2, cudaStreamNonBlocking);
        cudaEventCreateWithFlags(&evFork, cudaEventDisableTiming);
        cudaEventCreateWithFlags(&evWhf,  cudaEventDisableTiming);
        cudaEventCreateWithFlags(&evW,    cudaEventDisableTiming);
        init_done = true;
    }

    // fork side streams off the main stream
    cudaEventRecord(evFork, 0);
    cudaStreamWaitEvent(s1, evFork, 0);
    cudaStreamWaitEvent(s2, evFork, 0);

    // s1: Wh -> fragment bf16 hi/lo (needed by scan)
    {
        dim3 grid(38, 200);
        k_cvt_whf<<<grid, 128, 0, s1>>>(Wh);
        cudaEventRecord(evWhf, s1);
    }
    // s2: Wout -> bf16 hi/lo (needed only by k_out)
    {
        dim3 grid((NPADW / 8 + 255) / 256, KPAD);
        k_cvt_w<<<grid, 256, 0, s2>>>(Wout);
        cudaEventRecord(evW, s2);
    }
    // main: Wi conversion then GI GEMM (side streams overlap this)
    k_cvt_wi<<<(T_ * GI_KP * 80 + 255) / 256, 256>>>(Wi);
    {
        dim3 grid(8, 200);
        k_gi_mma<<<grid, 512, GI3_SMEM>>>(q, f, eq, ef, bi);
    }
    // join whf, run scan
    cudaStreamWaitEvent(0, evWhf, 0);
    k_scan_mma<<<128, 608, SCAN_SMEM>>>(bhn, ic);
    // join w, run output GEMM
    cudaStreamWaitEvent(0, evW, 0);
    {
        dim3 grid(8, NT3);
        k_out_mma<<<grid, 512, MMA_SMEM>>>(bout, out);
    }
}

// round 15
// speedup vs baseline: 1.0035x; 1.0035x over previous
#include <cuda_runtime.h>
#include <cuda_bf16.h>
#include <cstdint>

// Problem constants
#define B_   1024
#define T_   200
#define E_   100
#define H_   200
#define G3_  600      // 3*H
#define NITEMS 100000

#define KPAD 256             // K padded storage for output GEMM operands
#define NT3  391             // ceil(100000/256)
#define NPADW (NT3*256)      // 100096

#define GI_KP 112            // K pad for GI GEMM
#define GI_NP 640            // N pad for GI GEMM

// Scratch (device globals; allocation is forbidden)
__device__ float g_GI[(size_t)T_ * B_ * G3_]; // gi = x@Wi+bi  [t][b][600]

// bf16 hi/lo operands for the mma.sync output GEMM
__device__ __nv_bfloat16 g_w_hi[(size_t)KPAD * NPADW];  // [k][n]
__device__ __nv_bfloat16 g_w_lo[(size_t)KPAD * NPADW];
__device__ __nv_bfloat16 g_h_hi[B_ * KPAD];             // [m][k]
__device__ __nv_bfloat16 g_h_lo[B_ * KPAD];
// Wh pre-fragged for scan mma: [t][mt 40][ks 13][lane 32] uint4
__device__ uint4 g_whf_hi[(size_t)T_ * 40 * 13 * 32];
__device__ uint4 g_whf_lo[(size_t)T_ * 40 * 13 * 32];
// Wi linear bf16 hi/lo for GI GEMM: [t][112][640]
__device__ __nv_bfloat16 g_wi_hi[(size_t)T_ * GI_KP * GI_NP];
__device__ __nv_bfloat16 g_wi_lo[(size_t)T_ * GI_KP * GI_NP];

static __device__ __forceinline__ float tanh_fast(float x) {
    float y; asm("tanh.approx.f32 %0, %1;" : "=f"(y) : "f"(x)); return y;
}
static __device__ __forceinline__ float sig_fast(float x) {
    return fmaf(tanh_fast(0.5f * x), 0.5f, 0.5f);
}
static __device__ __forceinline__ uint32_t smem_u32(const void* p) {
    uint32_t a;
    asm("{ .reg .u64 t; cvta.to.shared.u64 t, %1; cvt.u32.u64 %0, t; }" : "=r"(a) : "l"(p));
    return a;
}

// ---------------- mma.sync helpers ----------------
static __device__ __forceinline__ void ldmA(uint32_t* r, uint32_t addr) {
    asm volatile("ldmatrix.sync.aligned.m8n8.x4.shared.b16 {%0,%1,%2,%3}, [%4];"
        : "=r"(r[0]), "=r"(r[1]), "=r"(r[2]), "=r"(r[3]) : "r"(addr));
}
static __device__ __forceinline__ void ldmBT(uint32_t* r, uint32_t addr) {
    asm volatile("ldmatrix.sync.aligned.m8n8.x4.trans.shared.b16 {%0,%1,%2,%3}, [%4];"
        : "=r"(r[0]), "=r"(r[1]), "=r"(r[2]), "=r"(r[3]) : "r"(addr));
}
static __device__ __forceinline__ void mma_bf16(float* c, const uint32_t* a, const uint32_t* b) {
    asm volatile("mma.sync.aligned.m16n8k16.row.col.f32.bf16.bf16.f32 "
        "{%0,%1,%2,%3}, {%4,%5,%6,%7}, {%8,%9}, {%0,%1,%2,%3};"
        : "+f"(c[0]), "+f"(c[1]), "+f"(c[2]), "+f"(c[3])
        : "r"(a[0]), "r"(a[1]), "r"(a[2]), "r"(a[3]), "r"(b[0]), "r"(b[1]));
}
static __device__ __forceinline__ void bf_split(float v, unsigned short& h, unsigned short& l) {
    __nv_bfloat16 hh = __float2bfloat16(v);
    h = __bfloat16_as_ushort(hh);
    l = __bfloat16_as_ushort(__float2bfloat16(v - __bfloat162float(hh)));
}
static __device__ __forceinline__ void pack_split2(float v0, float v1, uint32_t& hi2, uint32_t& lo2) {
    asm("cvt.rn.bf16x2.f32 %0, %1, %2;" : "=r"(hi2) : "f"(v1), "f"(v0));
    float h0 = __uint_as_float(hi2 << 16);
    float h1 = __uint_as_float((hi2 >> 16) << 16);
    asm("cvt.rn.bf16x2.f32 %0, %1, %2;" : "=r"(lo2) : "f"(v1 - h1), "f"(v0 - h0));
}
static __device__ __forceinline__ void cp16(uint32_t dst, const void* src) {
    asm volatile("cp.async.cg.shared.global [%0], [%1], 16;" :: "r"(dst), "l"(src) : "memory");
}

// ---------------------------------------------------------------------------
// Wi conversion: [200][100][600] fp32 -> linear [200][112][640] bf16 hi/lo
// ---------------------------------------------------------------------------
__global__ void k_cvt_wi(const float* __restrict__ Wi) {
    int idx = blockIdx.x * 256 + threadIdx.x;   // 200*112*80
    if (idx >= T_ * GI_KP * 80) return;
    int n8 = idx % 80;
    int k  = (idx / 80) % GI_KP;
    int t  = idx / (80 * GI_KP);
    int n  = n8 * 8;

    union { unsigned short u[8]; uint4 v; } ph, pl;
    #pragma unroll
    for (int j = 0; j < 8; ++j) {
        float v = (k < E_ && n + j < G3_) ? __ldg(Wi + ((size_t)t * E_ + k) * G3_ + n + j) : 0.f;
        bf_split(v, ph.u[j], pl.u[j]);
    }
    size_t dst = ((size_t)t * GI_KP + k) * GI_NP + n;
    *(uint4*)(g_wi_hi + dst) = ph.v;
    *(uint4*)(g_wi_lo + dst) = pl.v;
}

// ---------------------------------------------------------------------------
// K2 mma v3: grid (bt 8, t 200); per CTA M=128 x N=640 x K=112.
// ---------------------------------------------------------------------------
#define GIA_STR 120
#define GIB_STR 136
#define GI3_A_BYTES (128 * GIA_STR * 2)
#define GI3_B_SPLIT (GI_KP * GIB_STR * 2)
#define GI3_B_BUF   (2 * GI3_B_SPLIT)
#define GI3_SMEM    (2 * GI3_A_BYTES + 2 * GI3_B_BUF)   // 183296

__global__ void __launch_bounds__(512, 1)
k_gi_mma(const int* __restrict__ q, const int* __restrict__ f,
         const float* __restrict__ eq, const float* __restrict__ ef,
         const float* __restrict__ bi) {
    extern __shared__ char sm[];
    __nv_bfloat16* sAh = (__nv_bfloat16*)sm;
    __nv_bfloat16* sAl = (__nv_bfloat16*)(sm + GI3_A_BYTES);
    char* sB = sm + 2 * GI3_A_BYTES;
    __shared__ int sq[128], sf[128];
    __shared__ float sbi[608];

    const int tid  = threadIdx.x;
    const int wid  = tid >> 5, lane = tid & 31;
    const int bt   = blockIdx.x;
    const int t    = blockIdx.y;
    const int wm   = wid & 1;
    const int wn   = wid >> 1;
    const int b_base = bt * 128;

    const uint32_t sB32 = smem_u32(sB);
    auto fillB = [&](int c, int p) {
        size_t srcbase = (size_t)t * GI_KP * GI_NP + c * 128;
        uint32_t dstbase = sB32 + p * GI3_B_BUF;
        for (int i = tid; i < 3584; i += 512) {
            int split = i / 1792;
            int r = i - split * 1792;
            int k = r >> 4, j = r & 15;
            const __nv_bfloat16* src = (split ? g_wi_lo : g_wi_hi) + srcbase + (size_t)k * GI_NP + j * 8;
            uint32_t dst = dstbase + split * GI3_B_SPLIT + (k * GIB_STR + j * 8) * 2;
            cp16(dst, src);
        }
        asm volatile("cp.async.commit_group;" ::: "memory");
    };

    fillB(0, 0);

    if (tid < 128) {
        sq[tid] = __ldg(q + (b_base + tid) * T_ + t);
        sf[tid] = __ldg(f + (b_base + tid) * T_ + t);
    }
    for (int i = tid; i < G3_; i += 512)
        sbi[i] = __ldg(bi + t * G3_ + i);
    __syncthreads();

    for (int i = tid; i < 128 * 25; i += 512) {
        int m = i / 25, c4 = i - m * 25;
        int k0 = c4 * 4;
        float4 a = __ldg((const float4*)(eq + sq[m] * E_ + k0));
        float4 b = __ldg((const float4*)(ef + sf[m] * E_ + k0));
        float vv[4] = {a.x * b.x, a.y * b.y, a.z * b.z, a.w * b.w};
        union { unsigned short u[4]; uint2 v; } ph, pl;
        #pragma unroll
        for (int j = 0; j < 4; ++j) bf_split(vv[j], ph.u[j], pl.u[j]);
        *(uint2*)(sAh + m * GIA_STR + k0) = ph.v;
        *(uint2*)(sAl + m * GIA_STR + k0) = pl.v;
    }
    for (int i = tid; i < 128 * 6; i += 512) {
        int m = i / 6, kk = 100 + 2 * (i - m * 6);
        *(uint32_t*)(sAh + m * GIA_STR + kk) = 0;
        *(uint32_t*)(sAl + m * GIA_STR + kk) = 0;
    }

    const uint32_t sAh32 = smem_u32(sAh), sAl32 = smem_u32(sAl);

    for (int c = 0; c < 5; ++c) {
        if (c + 1 < 5) {
            fillB(c + 1, (c + 1) & 1);
            asm volatile("cp.async.wait_group 1;" ::: "memory");
        } else {
            asm volatile("cp.async.wait_group 0;" ::: "memory");
        }
        __syncthreads();

        const uint32_t bh32 = sB32 + (c & 1) * GI3_B_BUF;
        const uint32_t bl32 = bh32 + GI3_B_SPLIT;

        float acc[4][2][4];
        #pragma unroll
        for (int i = 0; i < 4; ++i)
            #pragma unroll
            for (int j = 0; j < 2; ++j)
                #pragma unroll
                for (int k = 0; k < 4; ++k) acc[i][j][k] = 0.f;

        #pragma unroll
        for (int ks = 0; ks < 7; ++ks) {
            uint32_t Ah[4][4], Al[4][4];
            #pragma unroll
            for (int fm = 0; fm < 4; ++fm) {
                uint32_t off = ((wm * 64 + fm * 16 + (lane & 15)) * GIA_STR
                                + ks * 16 + (lane >> 4) * 8) * 2;
                ldmA(Ah[fm], sAh32 + off);
                ldmA(Al[fm], sAl32 + off);
            }
            uint32_t Bh[2][2], Bl[2][2];
            {
                uint32_t off = ((ks * 16 + (lane & 15)) * GIB_STR
                                + wn * 16 + (lane >> 4) * 8) * 2;
                uint32_t r[4];
                ldmBT(r, bh32 + off);
                Bh[0][0] = r[0]; Bh[0][1] = r[1];
                Bh[1][0] = r[2]; Bh[1][1] = r[3];
                ldmBT(r, bl32 + off);
                Bl[0][0] = r[0]; Bl[0][1] = r[1];
                Bl[1][0] = r[2]; Bl[1][1] = r[3];
            }
            #pragma unroll
            for (int fm = 0; fm < 4; ++fm)
                #pragma unroll
                for (int fn = 0; fn < 2; ++fn) {
                    mma_bf16(acc[fm][fn], Ah[fm], Bh[fn]);
                    mma_bf16(acc[fm][fn], Ah[fm], Bl[fn]);
                    mma_bf16(acc[fm][fn], Al[fm], Bh[fn]);
                }
        }

        #pragma unroll
        for (int fm = 0; fm < 4; ++fm) {
            int gm = b_base + wm * 64 + fm * 16 + (lane >> 2);
            #pragma unroll
            for (int fn = 0; fn < 2; ++fn) {
                int gn = c * 128 + wn * 16 + fn * 8 + (lane & 3) * 2;
                if (gn < G3_) {
                    float2 bv = *(float2*)&sbi[gn];
                    float2 o0 = make_float2(acc[fm][fn][0] + bv.x, acc[fm][fn][1] + bv.y);
                    float2 o1 = make_float2(acc[fm][fn][2] + bv.x, acc[fm][fn][3] + bv.y);
                    *(float2*)(g_GI + ((size_t)t * B_ + gm) * G3_ + gn) = o0;
                    *(float2*)(g_GI + ((size_t)t * B_ + gm + 8) * G3_ + gn) = o1;
                }
            }
        }
        __syncthreads();
    }
}

// ---------------------------------------------------------------------------
// Wh -> fragment layout conversion (once).
// ---------------------------------------------------------------------------
__global__ void __launch_bounds__(128)
k_cvt_whf(const float* __restrict__ Wh) {
    __shared__ float sA[208][17];
    const int mt = blockIdx.x;   // 0..37
    const int t  = blockIdx.y;
    const int tid = threadIdx.x;
    const int m0 = mt * 16;

    for (int i = tid; i < 208 * 16; i += 128) {
        int k = i >> 4, mm = i & 15;
        int m = m0 + mm;
        float v = (k < H_ && m < G3_) ? __ldg(Wh + ((size_t)t * H_ + k) * G3_ + m) : 0.f;
        sA[k][mm] = v;
    }
    __syncthreads();

    const int wid = tid >> 5, lane = tid & 31;
    const int g = lane >> 2, c = lane & 3;
    for (int ks = wid; ks < 13; ks += 4) {
        int k0 = ks * 16 + 2 * c;
        uint4 uh, ul;
        pack_split2(sA[k0][g],       sA[k0 + 1][g],     uh.x, ul.x);
        pack_split2(sA[k0][g + 8],   sA[k0 + 1][g + 8], uh.y, ul.y);
        pack_split2(sA[k0 + 8][g],   sA[k0 + 9][g],     uh.z, ul.z);
        pack_split2(sA[k0 + 8][g+8], sA[k0 + 9][g + 8], uh.w, ul.w);
        size_t idx = (((size_t)t * 40 + mt) * 13 + ks) * 32 + lane;
        g_whf_hi[idx] = uh;
        g_whf_lo[idx] = ul;
    }
}

// ---------------------------------------------------------------------------
// K3: GRU scan v8. 128 CTAs x 8 rows, 608 threads.
// tanh.approx gates, single-pass float4 gate phase.
// ---------------------------------------------------------------------------
#define SOFF_GI   0                      // [8][600] f32    19200
#define SOFF_GH   19200                  // [608][10] f32   24320
#define SOFF_HF   43520                  // [8][200] f32    6400
#define SOFF_HHI  49920                  // [8][132] u32    4224
#define SOFF_HLO  54144                  //                 4224
#define SOFF_BHN  58368                  // [200] f32       800
#define SCAN_SMEM 59168

#define WHF_S1    (19 * 13 * 32)
#define WHF_TSTEP (40 * 13 * 32)

__global__ void __launch_bounds__(608, 1)
k_scan_mma(const float* __restrict__ bhn, const float* __restrict__ ic) {
    extern __shared__ char sm[];
    float*    sgi = (float*)(sm + SOFF_GI);
    float*    sgh = (float*)(sm + SOFF_GH);
    float*    shf = (float*)(sm + SOFF_HF);
    uint32_t* hh  = (uint32_t*)(sm + SOFF_HHI);
    uint32_t* hl  = (uint32_t*)(sm + SOFF_HLO);
    float*    sbh = (float*)(sm + SOFF_BHN);

    const int tid  = threadIdx.x;
    const int wid  = tid >> 5, lane = tid & 31;
    const int b0   = blockIdx.x * 8;
    const int g    = lane >> 2, cc = lane & 3;
    const uint32_t sgi_a = smem_u32(sgi);
    const uint32_t sbh_a = smem_u32(sbh);

    for (int i = tid; i < 8 * 132; i += 608) {
        int w = i % 132;
        uint32_t hi2 = 0, lo2 = 0;
        if (w < 100) {
            float v0 = __ldg(ic + 2 * w), v1 = __ldg(ic + 2 * w + 1);
            pack_split2(v0, v1, hi2, lo2);
        }
        hh[i] = hi2; hl[i] = lo2;
    }
    for (int i = tid; i < 1600; i += 608)
        shf[i] = __ldg(ic + (i % 200));
    __syncthreads();

    float acc0a[4], acc0b[4], acc1a[4], acc1b[4];
    uint4 bh0[2], bl0[2], bh1[2], bl1[2];

    const uint4* ph = g_whf_hi + ((size_t)wid * 13) * 32 + lane;
    const uint4* pl = g_whf_lo + ((size_t)wid * 13) * 32 + lane;

    bh0[0] = __ldg(ph);               bl0[0] = __ldg(pl);
    bh1[0] = __ldg(ph + WHF_S1);      bl1[0] = __ldg(pl + WHF_S1);
    bh0[1] = __ldg(ph + 32);          bl0[1] = __ldg(pl + 32);
    bh1[1] = __ldg(ph + WHF_S1 + 32); bl1[1] = __ldg(pl + WHF_S1 + 32);

    for (int t = 0; t < T_; ++t) {
        {
            const float* gib = g_GI + ((size_t)t * B_ + b0) * G3_;
            for (int i = tid; i < 1250; i += 608) {
                if (i < 1200) {
                    int b = i / 150, o = (i - b * 150) * 16;
                    cp16(sgi_a + b * 2400 + o, (const char*)(gib + b * G3_) + o);
                } else {
                    int j = i - 1200;
                    cp16(sbh_a + j * 16, (const char*)(bhn + t * H_) + j * 16);
                }
            }
            asm volatile("cp.async.commit_group;" ::: "memory");
        }

        #pragma unroll
        for (int c = 0; c < 4; ++c) { acc0a[c] = 0.f; acc0b[c] = 0.f; acc1a[c] = 0.f; acc1b[c] = 0.f; }

        #pragma unroll
        for (int ks = 0; ks < 13; ++ks) {
            const int p = ks & 1;
            uint4 a0h = bh0[p], a0l = bl0[p], a1h = bh1[p], a1l = bl1[p];
            if (ks + 2 < 13) {
                int off = (ks + 2) * 32;
                bh0[p] = __ldg(ph + off);          bl0[p] = __ldg(pl + off);
                bh1[p] = __ldg(ph + WHF_S1 + off); bl1[p] = __ldg(pl + WHF_S1 + off);
            }
            int r0 = g * 132 + ks * 8 + cc;
            uint32_t Bh[2] = { hh[r0], hh[r0 + 4] };
            uint32_t Bl[2] = { hl[r0], hl[r0 + 4] };
            uint32_t Ah0[4] = {a0h.x, a0h.y, a0h.z, a0h.w};
            uint32_t Al0[4] = {a0l.x, a0l.y, a0l.z, a0l.w};
            uint32_t Ah1[4] = {a1h.x, a1h.y, a1h.z, a1h.w};
            uint32_t Al1[4] = {a1l.x, a1l.y, a1l.z, a1l.w};
            mma_bf16(acc0a, Ah0, Bh);
            mma_bf16(acc1a, Ah1, Bh);
            mma_bf16(acc0b, Ah0, Bl);
            mma_bf16(acc1b, Ah1, Bl);
            mma_bf16(acc0b, Al0, Bh);
            mma_bf16(acc1b, Al1, Bh);
        }

        {
            int m0 = wid * 16;
            *(float2*)&sgh[(m0 + g) * 10 + cc * 2]     = make_float2(acc0a[0] + acc0b[0], acc0a[1] + acc0b[1]);
            *(float2*)&sgh[(m0 + g + 8) * 10 + cc * 2] = make_float2(acc0a[2] + acc0b[2], acc0a[3] + acc0b[3]);
            int m1 = (wid + 19) * 16;
            *(float2*)&sgh[(m1 + g) * 10 + cc * 2]     = make_float2(acc1a[0] + acc1b[0], acc1a[1] + acc1b[1]);
            *(float2*)&sgh[(m1 + g + 8) * 10 + cc * 2] = make_float2(acc1a[2] + acc1b[2], acc1a[3] + acc1b[3]);
        }

        if (t + 1 < T_) {
            ph += WHF_TSTEP;
            pl += WHF_TSTEP;
            bh0[0] = __ldg(ph);               bl0[0] = __ldg(pl);
            bh1[0] = __ldg(ph + WHF_S1);      bl1[0] = __ldg(pl + WHF_S1);
            bh0[1] = __ldg(ph + 32);          bl0[1] = __ldg(pl + 32);
            bh1[1] = __ldg(ph + WHF_S1 + 32); bl1[1] = __ldg(pl + WHF_S1 + 32);
        }

        asm volatile("cp.async.wait_group 0;" ::: "memory");
        __syncthreads();

        // gate phase: single pass, 400 float4 items (b, j quad)
        if (tid < 400) {
            int b = tid / 50, jq = tid - b * 50;
            int j = jq * 4;
            const float* gib = sgi + b * G3_;
            float4 gr = *(const float4*)(gib + j);
            float4 gz = *(const float4*)(gib + 200 + j);
            float4 gn = *(const float4*)(gib + 400 + j);
            float4 bv = *(const float4*)(sbh + j);
            float4 ho = *(const float4*)(shf + b * 200 + j);
            float hr[4], hz[4], hn_[4];
            #pragma unroll
            for (int d = 0; d < 4; ++d) {
                hr[d]  = sgh[(j + d) * 10 + b];
                hz[d]  = sgh[(200 + j + d) * 10 + b];
                hn_[d] = sgh[(400 + j + d) * 10 + b];
            }
            float grr[4] = {gr.x, gr.y, gr.z, gr.w};
            float gzz[4] = {gz.x, gz.y, gz.z, gz.w};
            float gnn[4] = {gn.x, gn.y, gn.z, gn.w};
            float bvv[4] = {bv.x, bv.y, bv.z, bv.w};
            float hoo[4] = {ho.x, ho.y, ho.z, ho.w};
            float hnew[4];
            #pragma unroll
            for (int d = 0; d < 4; ++d) {
                float r = sig_fast(grr[d] + hr[d]);
                float z = sig_fast(gzz[d] + hz[d]);
                float n = tanh_fast(gnn[d] + r * (hn_[d] + bvv[d]));
                hnew[d] = (1.f - z) * n + z * hoo[d];
            }
            *(float4*)(shf + b * 200 + j) = make_float4(hnew[0], hnew[1], hnew[2], hnew[3]);
            uint32_t hiA, loA, hiB, loB;
            pack_split2(hnew[0], hnew[1], hiA, loA);
            pack_split2(hnew[2], hnew[3], hiB, loB);
            int jp = j >> 1;
            *(uint2*)&hh[b * 132 + jp] = make_uint2(hiA, hiB);
            *(uint2*)&hl[b * 132 + jp] = make_uint2(loA, loB);
        }
        __syncthreads();
    }

    // final: fused bf16 hi/lo conversion of hT for the output GEMM
    for (int i = tid; i < 8 * 128; i += 608) {
        int b = i / 128, kp = i - b * 128;
        int k0 = kp * 2;
        float v0 = (k0 < H_) ? shf[b * 200 + k0] : 0.f;
        float v1 = (k0 + 1 < H_) ? shf[b * 200 + k0 + 1] : 0.f;
        uint32_t hi2, lo2;
        pack_split2(v0, v1, hi2, lo2);
        *(uint32_t*)(g_h_hi + (size_t)(b0 + b) * KPAD + k0) = hi2;
        *(uint32_t*)(g_h_lo + (size_t)(b0 + b) * KPAD + k0) = lo2;
    }
}

// ---------------------------------------------------------------------------
// Wout conversion
// ---------------------------------------------------------------------------
__global__ void k_cvt_w(const float* __restrict__ Wout) {
    int nb = blockIdx.x * 256 + threadIdx.x;
    int k  = blockIdx.y;
    if (nb >= NPADW / 8) return;
    int n = nb * 8;

    union { unsigned short u[8]; uint4 v; } ph, pl;
    if (k < H_ && n + 7 < NITEMS) {
        const float4* src = (const float4*)(Wout + (size_t)k * NITEMS + n);
        float4 v0 = __ldg(src), v1 = __ldg(src + 1);
        float vv[8] = {v0.x, v0.y, v0.z, v0.w, v1.x, v1.y, v1.z, v1.w};
        #pragma unroll
        for (int j = 0; j < 8; ++j) bf_split(vv[j], ph.u[j], pl.u[j]);
    } else {
        #pragma unroll
        for (int j = 0; j < 8; ++j) {
            float v = (k < H_ && n + j < NITEMS) ? __ldg(Wout + (size_t)k * NITEMS + n + j) : 0.f;
            bf_split(v, ph.u[j], pl.u[j]);
        }
    }
    *(uint4*)(g_w_hi + (size_t)k * NPADW + n) = ph.v;
    *(uint4*)(g_w_lo + (size_t)k * NPADW + n) = pl.v;
}

// ---------------------------------------------------------------------------
// K4 mma.sync v3: 512 threads, BN=256, K=208 (chunks 64/64/64/16), cp.async.
// ---------------------------------------------------------------------------
#define OASTR 72
#define OBSTR 264
#define OUT_AB (128 * OASTR * 2)
#define OUT_BB (64 * OBSTR * 2)
#define OUT_BUF (2 * OUT_AB + 2 * OUT_BB)
#define MMA_SMEM (2 * OUT_BUF)              // 208896

__global__ void __launch_bounds__(512, 1)
k_out_mma(const float* __restrict__ bout, float* __restrict__ out) {
    extern __shared__ char smc[];
    const int tid  = threadIdx.x;
    const int wid  = tid >> 5, lane = tid & 31;
    const int mt   = blockIdx.x;
    const int nt   = blockIdx.y;
    const int wm   = wid & 1;
    const int wn   = wid >> 1;
    const uint32_t sbase = smem_u32(smc);

    auto fill = [&](int kc, int p) {
        const int nk = (kc < 3) ? 4 : 1;
        const int k0 = kc * 64;
        uint32_t buf = sbase + p * OUT_BUF;
        int per = nk * 2;
        int aTot = 2 * 128 * per;
        for (int i = tid; i < aTot; i += 512) {
            int split = i / (128 * per);
            int r = i - split * 128 * per;
            int m = r / per, kb = r - m * per;
            const __nv_bfloat16* src = (split ? g_h_lo : g_h_hi)
                + (size_t)(mt * 128 + m) * KPAD + k0 + kb * 8;
            cp16(buf + split * OUT_AB + (m * OASTR + kb * 8) * 2, src);
        }
        int rows = nk * 16;
        int bTot = 2 * rows * 32;
        for (int i = tid; i < bTot; i += 512) {
            int split = i / (rows * 32);
            int r = i - split * rows * 32;
            int k = r >> 5, nb = r & 31;
            const __nv_bfloat16* src = (split ? g_w_lo : g_w_hi)
                + (size_t)(k0 + k) * NPADW + nt * 256 + nb * 8;
            cp16(buf + 2 * OUT_AB + split * OUT_BB + (k * OBSTR + nb * 8) * 2, src);
        }
        asm volatile("cp.async.commit_group;" ::: "memory");
    };

    fill(0, 0);

    float acc[4][4][4];
    #pragma unroll
    for (int i = 0; i < 4; ++i)
        #pragma unroll
        for (int j = 0; j < 4; ++j)
            #pragma unroll
            for (int c = 0; c < 4; ++c) acc[i][j][c] = 0.f;

    for (int kc = 0; kc < 4; ++kc) {
        if (kc + 1 < 4) {
            fill(kc + 1, (kc + 1) & 1);
            asm volatile("cp.async.wait_group 1;" ::: "memory");
        } else {
            asm volatile("cp.async.wait_group 0;" ::: "memory");
        }
        __syncthreads();

        uint32_t buf = sbase + (kc & 1) * OUT_BUF;
        const uint32_t sAh32 = buf, sAl32 = buf + OUT_AB;
        const uint32_t sBh32 = buf + 2 * OUT_AB, sBl32 = sBh32 + OUT_BB;
        const int nk = (kc < 3) ? 4 : 1;

        #pragma unroll 4
        for (int ks = 0; ks < nk; ++ks) {
            uint32_t Ah[4][4], Al[4][4];
            #pragma unroll
            for (int fm = 0; fm < 4; ++fm) {
                uint32_t off = ((wm * 64 + fm * 16 + (lane & 15)) * OASTR
                                + ks * 16 + (lane >> 4) * 8) * 2;
                ldmA(Ah[fm], sAh32 + off);
                ldmA(Al[fm], sAl32 + off);
            }
            uint32_t Bh[4][2], Bl[4][2];
            #pragma unroll
            for (int fb = 0; fb < 2; ++fb) {
                uint32_t off = ((ks * 16 + (lane & 15)) * OBSTR
                                + wn * 32 + fb * 16 + (lane >> 4) * 8) * 2;
                uint32_t r[4];
                ldmBT(r, sBh32 + off);
                Bh[fb*2][0] = r[0]; Bh[fb*2][1] = r[1];
                Bh[fb*2+1][0] = r[2]; Bh[fb*2+1][1] = r[3];
                ldmBT(r, sBl32 + off);
                Bl[fb*2][0] = r[0]; Bl[fb*2][1] = r[1];
                Bl[fb*2+1][0] = r[2]; Bl[fb*2+1][1] = r[3];
            }
            #pragma unroll
            for (int fm = 0; fm < 4; ++fm)
                #pragma unroll
                for (int fn = 0; fn < 4; ++fn) {
                    mma_bf16(acc[fm][fn], Ah[fm], Bh[fn]);
                    mma_bf16(acc[fm][fn], Ah[fm], Bl[fn]);
                    mma_bf16(acc[fm][fn], Al[fm], Bh[fn]);
                }
        }
        __syncthreads();
    }

    #pragma unroll
    for (int fm = 0; fm < 4; ++fm) {
        int gm = mt * 128 + wm * 64 + fm * 16 + (lane >> 2);
        #pragma unroll
        for (int fn = 0; fn < 4; ++fn) {
            int gn = nt * 256 + wn * 32 + fn * 8 + (lane & 3) * 2;
            if (gn < NITEMS) {
                float2 bv = __ldg((const float2*)(bout + gn));
                float2 o0 = make_float2(acc[fm][fn][0] + bv.x, acc[fm][fn][1] + bv.y);
                float2 o1 = make_float2(acc[fm][fn][2] + bv.x, acc[fm][fn][3] + bv.y);
                *(float2*)(out + (size_t)gm * NITEMS + gn) = o0;
                *(float2*)(out + (size_t)(gm + 8) * NITEMS + gn) = o1;
            }
        }
    }
}

// ---------------------------------------------------------------------------
extern "C" void kernel_launch(void* const* d_in, const int* in_sizes, int n_in,
                              void* d_out, int out_size) {
    const int*   q    = (const int*)  d_in[0];
    const int*   f    = (const int*)  d_in[1];
    const float* eq   = (const float*)d_in[2];
    const float* ef   = (const float*)d_in[3];
    const float* ic   = (const float*)d_in[4];
    const float* Wi   = (const float*)d_in[5];
    const float* bi   = (const float*)d_in[6];
    const float* Wh   = (const float*)d_in[7];
    const float* bhn  = (const float*)d_in[8];
    const float* Wout = (const float*)d_in[9];
    const float* bout = (const float*)d_in[10];
    float* out = (float*)d_out;

    static bool attr_done = false;
    if (!attr_done) {
        cudaFuncSetAttribute(k_gi_mma,   cudaFuncAttributeMaxDynamicSharedMemorySize, GI3_SMEM);
        cudaFuncSetAttribute(k_scan_mma, cudaFuncAttributeMaxDynamicSharedMemorySize, SCAN_SMEM);
        cudaFuncSetAttribute(k_out_mma,  cudaFuncAttributeMaxDynamicSharedMemorySize, MMA_SMEM);
        attr_done = true;
    }

    // Wout -> bf16 hi/lo
    {
        dim3 grid((NPADW / 8 + 255) / 256, KPAD);
        k_cvt_w<<<grid, 256>>>(Wout);
    }
    // Wi -> linear bf16 hi/lo
    k_cvt_wi<<<(T_ * GI_KP * 80 + 255) / 256, 256>>>(Wi);
    // Wh -> fragment bf16 hi/lo (38 mtiles used)
    {
        dim3 grid(38, 200);
        k_cvt_whf<<<grid, 128>>>(Wh);
    }
    // GI = (gathered state) @ Wi + bi
    {
        dim3 grid(8, 200);
        k_gi_mma<<<grid, 512, GI3_SMEM>>>(q, f, eq, ef, bi);
    }
    // GRU scan (tensor cores, tanh.approx gates)
    k_scan_mma<<<128, 608, SCAN_SMEM>>>(bhn, ic);
    // out = hT @ Wout + bout (tensor cores, 16 warps, K=208, BN=256)
    {
        dim3 grid(8, NT3);
        k_out_mma<<<grid, 512, MMA_SMEM>>>(bout, out);
    }
}

// round 16
// speedup vs baseline: 1.0250x; 1.0215x over previous
#include <cuda_runtime.h>
#include <cuda_bf16.h>
#include <cstdint>

// Problem constants
#define B_   1024
#define T_   200
#define E_   100
#define H_   200
#define G3_  600      // 3*H
#define NITEMS 100000

#define KPAD 256             // K padded storage for output GEMM operands
#define NT3  391             // ceil(100000/256)
#define NPADW (NT3*256)      // 100096

#define GI_KP 112            // K pad for GI GEMM
#define GI_NP 640            // N pad for GI GEMM

// Scratch (device globals; allocation is forbidden)
__device__ float g_GI[(size_t)T_ * B_ * G3_]; // gi = x@Wi+bi  [t][b][600]

// bf16 hi/lo operands for the mma.sync output GEMM
__device__ __nv_bfloat16 g_w_hi[(size_t)KPAD * NPADW];  // [k][n]
__device__ __nv_bfloat16 g_w_lo[(size_t)KPAD * NPADW];
__device__ __nv_bfloat16 g_h_hi[B_ * KPAD];             // [m][k]
__device__ __nv_bfloat16 g_h_lo[B_ * KPAD];
// Wh pre-fragged for scan mma: [t][mt 40][ks 13][lane 32] uint4
__device__ uint4 g_whf_hi[(size_t)T_ * 40 * 13 * 32];
__device__ uint4 g_whf_lo[(size_t)T_ * 40 * 13 * 32];
// Wi linear bf16 hi/lo for GI GEMM: [t][112][640]
__device__ __nv_bfloat16 g_wi_hi[(size_t)T_ * GI_KP * GI_NP];
__device__ __nv_bfloat16 g_wi_lo[(size_t)T_ * GI_KP * GI_NP];

static __device__ __forceinline__ float tanh_fast(float x) {
    float y; asm("tanh.approx.f32 %0, %1;" : "=f"(y) : "f"(x)); return y;
}
static __device__ __forceinline__ float sig_fast(float x) {
    return fmaf(tanh_fast(0.5f * x), 0.5f, 0.5f);
}
static __device__ __forceinline__ uint32_t smem_u32(const void* p) {
    uint32_t a;
    asm("{ .reg .u64 t; cvta.to.shared.u64 t, %1; cvt.u32.u64 %0, t; }" : "=r"(a) : "l"(p));
    return a;
}

// ---------------- mma.sync helpers ----------------
static __device__ __forceinline__ void ldmA(uint32_t* r, uint32_t addr) {
    asm volatile("ldmatrix.sync.aligned.m8n8.x4.shared.b16 {%0,%1,%2,%3}, [%4];"
        : "=r"(r[0]), "=r"(r[1]), "=r"(r[2]), "=r"(r[3]) : "r"(addr));
}
static __device__ __forceinline__ void ldmBT(uint32_t* r, uint32_t addr) {
    asm volatile("ldmatrix.sync.aligned.m8n8.x4.trans.shared.b16 {%0,%1,%2,%3}, [%4];"
        : "=r"(r[0]), "=r"(r[1]), "=r"(r[2]), "=r"(r[3]) : "r"(addr));
}
static __device__ __forceinline__ void mma_bf16(float* c, const uint32_t* a, const uint32_t* b) {
    asm volatile("mma.sync.aligned.m16n8k16.row.col.f32.bf16.bf16.f32 "
        "{%0,%1,%2,%3}, {%4,%5,%6,%7}, {%8,%9}, {%0,%1,%2,%3};"
        : "+f"(c[0]), "+f"(c[1]), "+f"(c[2]), "+f"(c[3])
        : "r"(a[0]), "r"(a[1]), "r"(a[2]), "r"(a[3]), "r"(b[0]), "r"(b[1]));
}
static __device__ __forceinline__ void bf_split(float v, unsigned short& h, unsigned short& l) {
    __nv_bfloat16 hh = __float2bfloat16(v);
    h = __bfloat16_as_ushort(hh);
    l = __bfloat16_as_ushort(__float2bfloat16(v - __bfloat162float(hh)));
}
static __device__ __forceinline__ void pack_split2(float v0, float v1, uint32_t& hi2, uint32_t& lo2) {
    asm("cvt.rn.bf16x2.f32 %0, %1, %2;" : "=r"(hi2) : "f"(v1), "f"(v0));
    float h0 = __uint_as_float(hi2 << 16);
    float h1 = __uint_as_float((hi2 >> 16) << 16);
    asm("cvt.rn.bf16x2.f32 %0, %1, %2;" : "=r"(lo2) : "f"(v1 - h1), "f"(v0 - h0));
}
static __device__ __forceinline__ void cp16(uint32_t dst, const void* src) {
    asm volatile("cp.async.cg.shared.global [%0], [%1], 16;" :: "r"(dst), "l"(src) : "memory");
}

// ---------------------------------------------------------------------------
// Wi conversion: [200][100][600] fp32 -> linear [200][112][640] bf16 hi/lo
// ---------------------------------------------------------------------------
__global__ void k_cvt_wi(const float* __restrict__ Wi) {
    int idx = blockIdx.x * 256 + threadIdx.x;   // 200*112*80
    if (idx >= T_ * GI_KP * 80) return;
    int n8 = idx % 80;
    int k  = (idx / 80) % GI_KP;
    int t  = idx / (80 * GI_KP);
    int n  = n8 * 8;

    union { unsigned short u[8]; uint4 v; } ph, pl;
    #pragma unroll
    for (int j = 0; j < 8; ++j) {
        float v = (k < E_ && n + j < G3_) ? __ldg(Wi + ((size_t)t * E_ + k) * G3_ + n + j) : 0.f;
        bf_split(v, ph.u[j], pl.u[j]);
    }
    size_t dst = ((size_t)t * GI_KP + k) * GI_NP + n;
    *(uint4*)(g_wi_hi + dst) = ph.v;
    *(uint4*)(g_wi_lo + dst) = pl.v;
}

// ---------------------------------------------------------------------------
// K2 mma v3: grid (bt 8, t 200); per CTA M=128 x N=640 x K=112.
// ---------------------------------------------------------------------------
#define GIA_STR 120
#define GIB_STR 136
#define GI3_A_BYTES (128 * GIA_STR * 2)
#define GI3_B_SPLIT (GI_KP * GIB_STR * 2)
#define GI3_B_BUF   (2 * GI3_B_SPLIT)
#define GI3_SMEM    (2 * GI3_A_BYTES + 2 * GI3_B_BUF)   // 183296

__global__ void __launch_bounds__(512, 1)
k_gi_mma(const int* __restrict__ q, const int* __restrict__ f,
         const float* __restrict__ eq, const float* __restrict__ ef,
         const float* __restrict__ bi) {
    extern __shared__ char sm[];
    __nv_bfloat16* sAh = (__nv_bfloat16*)sm;
    __nv_bfloat16* sAl = (__nv_bfloat16*)(sm + GI3_A_BYTES);
    char* sB = sm + 2 * GI3_A_BYTES;
    __shared__ int sq[128], sf[128];
    __shared__ float sbi[608];

    const int tid  = threadIdx.x;
    const int wid  = tid >> 5, lane = tid & 31;
    const int bt   = blockIdx.x;
    const int t    = blockIdx.y;
    const int wm   = wid & 1;
    const int wn   = wid >> 1;
    const int b_base = bt * 128;

    const uint32_t sB32 = smem_u32(sB);
    auto fillB = [&](int c, int p) {
        size_t srcbase = (size_t)t * GI_KP * GI_NP + c * 128;
        uint32_t dstbase = sB32 + p * GI3_B_BUF;
        for (int i = tid; i < 3584; i += 512) {
            int split = i / 1792;
            int r = i - split * 1792;
            int k = r >> 4, j = r & 15;
            const __nv_bfloat16* src = (split ? g_wi_lo : g_wi_hi) + srcbase + (size_t)k * GI_NP + j * 8;
            uint32_t dst = dstbase + split * GI3_B_SPLIT + (k * GIB_STR + j * 8) * 2;
            cp16(dst, src);
        }
        asm volatile("cp.async.commit_group;" ::: "memory");
    };

    fillB(0, 0);

    if (tid < 128) {
        sq[tid] = __ldg(q + (b_base + tid) * T_ + t);
        sf[tid] = __ldg(f + (b_base + tid) * T_ + t);
    }
    for (int i = tid; i < G3_; i += 512)
        sbi[i] = __ldg(bi + t * G3_ + i);
    __syncthreads();

    for (int i = tid; i < 128 * 25; i += 512) {
        int m = i / 25, c4 = i - m * 25;
        int k0 = c4 * 4;
        float4 a = __ldg((const float4*)(eq + sq[m] * E_ + k0));
        float4 b = __ldg((const float4*)(ef + sf[m] * E_ + k0));
        float vv[4] = {a.x * b.x, a.y * b.y, a.z * b.z, a.w * b.w};
        union { unsigned short u[4]; uint2 v; } ph, pl;
        #pragma unroll
        for (int j = 0; j < 4; ++j) bf_split(vv[j], ph.u[j], pl.u[j]);
        *(uint2*)(sAh + m * GIA_STR + k0) = ph.v;
        *(uint2*)(sAl + m * GIA_STR + k0) = pl.v;
    }
    for (int i = tid; i < 128 * 6; i += 512) {
        int m = i / 6, kk = 100 + 2 * (i - m * 6);
        *(uint32_t*)(sAh + m * GIA_STR + kk) = 0;
        *(uint32_t*)(sAl + m * GIA_STR + kk) = 0;
    }

    const uint32_t sAh32 = smem_u32(sAh), sAl32 = smem_u32(sAl);

    for (int c = 0; c < 5; ++c) {
        if (c + 1 < 5) {
            fillB(c + 1, (c + 1) & 1);
            asm volatile("cp.async.wait_group 1;" ::: "memory");
        } else {
            asm volatile("cp.async.wait_group 0;" ::: "memory");
        }
        __syncthreads();

        const uint32_t bh32 = sB32 + (c & 1) * GI3_B_BUF;
        const uint32_t bl32 = bh32 + GI3_B_SPLIT;

        float acc[4][2][4];
        #pragma unroll
        for (int i = 0; i < 4; ++i)
            #pragma unroll
            for (int j = 0; j < 2; ++j)
                #pragma unroll
                for (int k = 0; k < 4; ++k) acc[i][j][k] = 0.f;

        #pragma unroll
        for (int ks = 0; ks < 7; ++ks) {
            uint32_t Ah[4][4], Al[4][4];
            #pragma unroll
            for (int fm = 0; fm < 4; ++fm) {
                uint32_t off = ((wm * 64 + fm * 16 + (lane & 15)) * GIA_STR
                                + ks * 16 + (lane >> 4) * 8) * 2;
                ldmA(Ah[fm], sAh32 + off);
                ldmA(Al[fm], sAl32 + off);
            }
            uint32_t Bh[2][2], Bl[2][2];
            {
                uint32_t off = ((ks * 16 + (lane & 15)) * GIB_STR
                                + wn * 16 + (lane >> 4) * 8) * 2;
                uint32_t r[4];
                ldmBT(r, bh32 + off);
                Bh[0][0] = r[0]; Bh[0][1] = r[1];
                Bh[1][0] = r[2]; Bh[1][1] = r[3];
                ldmBT(r, bl32 + off);
                Bl[0][0] = r[0]; Bl[0][1] = r[1];
                Bl[1][0] = r[2]; Bl[1][1] = r[3];
            }
            #pragma unroll
            for (int fm = 0; fm < 4; ++fm)
                #pragma unroll
                for (int fn = 0; fn < 2; ++fn) {
                    mma_bf16(acc[fm][fn], Ah[fm], Bh[fn]);
                    mma_bf16(acc[fm][fn], Ah[fm], Bl[fn]);
                    mma_bf16(acc[fm][fn], Al[fm], Bh[fn]);
                }
        }

        #pragma unroll
        for (int fm = 0; fm < 4; ++fm) {
            int gm = b_base + wm * 64 + fm * 16 + (lane >> 2);
            #pragma unroll
            for (int fn = 0; fn < 2; ++fn) {
                int gn = c * 128 + wn * 16 + fn * 8 + (lane & 3) * 2;
                if (gn < G3_) {
                    float2 bv = *(float2*)&sbi[gn];
                    float2 o0 = make_float2(acc[fm][fn][0] + bv.x, acc[fm][fn][1] + bv.y);
                    float2 o1 = make_float2(acc[fm][fn][2] + bv.x, acc[fm][fn][3] + bv.y);
                    *(float2*)(g_GI + ((size_t)t * B_ + gm) * G3_ + gn) = o0;
                    *(float2*)(g_GI + ((size_t)t * B_ + gm + 8) * G3_ + gn) = o1;
                }
            }
        }
        __syncthreads();
    }
}

// ---------------------------------------------------------------------------
// Wh -> fragment layout conversion (once).
// ---------------------------------------------------------------------------
__global__ void __launch_bounds__(128)
k_cvt_whf(const float* __restrict__ Wh) {
    __shared__ float sA[208][17];
    const int mt = blockIdx.x;   // 0..37
    const int t  = blockIdx.y;
    const int tid = threadIdx.x;
    const int m0 = mt * 16;

    for (int i = tid; i < 208 * 16; i += 128) {
        int k = i >> 4, mm = i & 15;
        int m = m0 + mm;
        float v = (k < H_ && m < G3_) ? __ldg(Wh + ((size_t)t * H_ + k) * G3_ + m) : 0.f;
        sA[k][mm] = v;
    }
    __syncthreads();

    const int wid = tid >> 5, lane = tid & 31;
    const int g = lane >> 2, c = lane & 3;
    for (int ks = wid; ks < 13; ks += 4) {
        int k0 = ks * 16 + 2 * c;
        uint4 uh, ul;
        pack_split2(sA[k0][g],       sA[k0 + 1][g],     uh.x, ul.x);
        pack_split2(sA[k0][g + 8],   sA[k0 + 1][g + 8], uh.y, ul.y);
        pack_split2(sA[k0 + 8][g],   sA[k0 + 9][g],     uh.z, ul.z);
        pack_split2(sA[k0 + 8][g+8], sA[k0 + 9][g + 8], uh.w, ul.w);
        size_t idx = (((size_t)t * 40 + mt) * 13 + ks) * 32 + lane;
        g_whf_hi[idx] = uh;
        g_whf_lo[idx] = ul;
    }
}

// ---------------------------------------------------------------------------
// K3: GRU scan v9. 128 CTAs x 8 rows, 608 threads.
// Round-13 gate loop structure + tanh.approx math.
// ---------------------------------------------------------------------------
#define SOFF_GI   0                      // [8][600] f32    19200
#define SOFF_GH   19200                  // [608][10] f32   24320
#define SOFF_HF   43520                  // [8][200] f32    6400
#define SOFF_HHI  49920                  // [8][132] u32    4224
#define SOFF_HLO  54144                  //                 4224
#define SOFF_BHN  58368                  // [200] f32       800
#define SCAN_SMEM 59168

#define WHF_S1    (19 * 13 * 32)
#define WHF_TSTEP (40 * 13 * 32)

__global__ void __launch_bounds__(608, 1)
k_scan_mma(const float* __restrict__ bhn, const float* __restrict__ ic) {
    extern __shared__ char sm[];
    float*    sgi = (float*)(sm + SOFF_GI);
    float*    sgh = (float*)(sm + SOFF_GH);
    float*    shf = (float*)(sm + SOFF_HF);
    uint32_t* hh  = (uint32_t*)(sm + SOFF_HHI);
    uint32_t* hl  = (uint32_t*)(sm + SOFF_HLO);
    float*    sbh = (float*)(sm + SOFF_BHN);

    const int tid  = threadIdx.x;
    const int wid  = tid >> 5, lane = tid & 31;
    const int b0   = blockIdx.x * 8;
    const int g    = lane >> 2, cc = lane & 3;
    const uint32_t sgi_a = smem_u32(sgi);
    const uint32_t sbh_a = smem_u32(sbh);

    for (int i = tid; i < 8 * 132; i += 608) {
        int w = i % 132;
        uint32_t hi2 = 0, lo2 = 0;
        if (w < 100) {
            float v0 = __ldg(ic + 2 * w), v1 = __ldg(ic + 2 * w + 1);
            pack_split2(v0, v1, hi2, lo2);
        }
        hh[i] = hi2; hl[i] = lo2;
    }
    for (int i = tid; i < 1600; i += 608)
        shf[i] = __ldg(ic + (i % 200));
    __syncthreads();

    float acc0a[4], acc0b[4], acc1a[4], acc1b[4];
    uint4 bh0[2], bl0[2], bh1[2], bl1[2];

    const uint4* ph = g_whf_hi + ((size_t)wid * 13) * 32 + lane;
    const uint4* pl = g_whf_lo + ((size_t)wid * 13) * 32 + lane;

    bh0[0] = __ldg(ph);               bl0[0] = __ldg(pl);
    bh1[0] = __ldg(ph + WHF_S1);      bl1[0] = __ldg(pl + WHF_S1);
    bh0[1] = __ldg(ph + 32);          bl0[1] = __ldg(pl + 32);
    bh1[1] = __ldg(ph + WHF_S1 + 32); bl1[1] = __ldg(pl + WHF_S1 + 32);

    for (int t = 0; t < T_; ++t) {
        {
            const float* gib = g_GI + ((size_t)t * B_ + b0) * G3_;
            for (int i = tid; i < 1250; i += 608) {
                if (i < 1200) {
                    int b = i / 150, o = (i - b * 150) * 16;
                    cp16(sgi_a + b * 2400 + o, (const char*)(gib + b * G3_) + o);
                } else {
                    int j = i - 1200;
                    cp16(sbh_a + j * 16, (const char*)(bhn + t * H_) + j * 16);
                }
            }
            asm volatile("cp.async.commit_group;" ::: "memory");
        }

        #pragma unroll
        for (int c = 0; c < 4; ++c) { acc0a[c] = 0.f; acc0b[c] = 0.f; acc1a[c] = 0.f; acc1b[c] = 0.f; }

        #pragma unroll
        for (int ks = 0; ks < 13; ++ks) {
            const int p = ks & 1;
            uint4 a0h = bh0[p], a0l = bl0[p], a1h = bh1[p], a1l = bl1[p];
            if (ks + 2 < 13) {
                int off = (ks + 2) * 32;
                bh0[p] = __ldg(ph + off);          bl0[p] = __ldg(pl + off);
                bh1[p] = __ldg(ph + WHF_S1 + off); bl1[p] = __ldg(pl + WHF_S1 + off);
            }
            int r0 = g * 132 + ks * 8 + cc;
            uint32_t Bh[2] = { hh[r0], hh[r0 + 4] };
            uint32_t Bl[2] = { hl[r0], hl[r0 + 4] };
            uint32_t Ah0[4] = {a0h.x, a0h.y, a0h.z, a0h.w};
            uint32_t Al0[4] = {a0l.x, a0l.y, a0l.z, a0l.w};
            uint32_t Ah1[4] = {a1h.x, a1h.y, a1h.z, a1h.w};
            uint32_t Al1[4] = {a1l.x, a1l.y, a1l.z, a1l.w};
            mma_bf16(acc0a, Ah0, Bh);
            mma_bf16(acc1a, Ah1, Bh);
            mma_bf16(acc0b, Ah0, Bl);
            mma_bf16(acc1b, Ah1, Bl);
            mma_bf16(acc0b, Al0, Bh);
            mma_bf16(acc1b, Al1, Bh);
        }

        {
            int m0 = wid * 16;
            *(float2*)&sgh[(m0 + g) * 10 + cc * 2]     = make_float2(acc0a[0] + acc0b[0], acc0a[1] + acc0b[1]);
            *(float2*)&sgh[(m0 + g + 8) * 10 + cc * 2] = make_float2(acc0a[2] + acc0b[2], acc0a[3] + acc0b[3]);
            int m1 = (wid + 19) * 16;
            *(float2*)&sgh[(m1 + g) * 10 + cc * 2]     = make_float2(acc1a[0] + acc1b[0], acc1a[1] + acc1b[1]);
            *(float2*)&sgh[(m1 + g + 8) * 10 + cc * 2] = make_float2(acc1a[2] + acc1b[2], acc1a[3] + acc1b[3]);
        }

        if (t + 1 < T_) {
            ph += WHF_TSTEP;
            pl += WHF_TSTEP;
            bh0[0] = __ldg(ph);               bl0[0] = __ldg(pl);
            bh1[0] = __ldg(ph + WHF_S1);      bl1[0] = __ldg(pl + WHF_S1);
            bh0[1] = __ldg(ph + 32);          bl0[1] = __ldg(pl + 32);
            bh1[1] = __ldg(ph + WHF_S1 + 32); bl1[1] = __ldg(pl + WHF_S1 + 32);
        }

        asm volatile("cp.async.wait_group 0;" ::: "memory");
        __syncthreads();

        // gate phase: 800 (b, j-pair) items (round-13 structure, tanh.approx math)
        for (int i = tid; i < 800; i += 608) {
            int b = i / 100, jp = i - b * 100, j = jp * 2;
            const float* gib = sgi + b * G3_;
            float2 gr = *(const float2*)(gib + j);
            float2 gz = *(const float2*)(gib + 200 + j);
            float2 gn = *(const float2*)(gib + 400 + j);
            float ghr0 = sgh[j * 10 + b],         ghr1 = sgh[(j + 1) * 10 + b];
            float ghz0 = sgh[(200 + j) * 10 + b], ghz1 = sgh[(201 + j) * 10 + b];
            float ghn0 = sgh[(400 + j) * 10 + b], ghn1 = sgh[(401 + j) * 10 + b];
            float2 bv = *(const float2*)(sbh + j);
            float2 ho = *(const float2*)(shf + b * 200 + j);
            float r0 = sig_fast(gr.x + ghr0), r1 = sig_fast(gr.y + ghr1);
            float z0 = sig_fast(gz.x + ghz0), z1 = sig_fast(gz.y + ghz1);
            float n0 = tanh_fast(gn.x + r0 * (ghn0 + bv.x));
            float n1 = tanh_fast(gn.y + r1 * (ghn1 + bv.y));
            float h0 = (1.f - z0) * n0 + z0 * ho.x;
            float h1 = (1.f - z1) * n1 + z1 * ho.y;
            *(float2*)(shf + b * 200 + j) = make_float2(h0, h1);
            uint32_t hi2, lo2;
            pack_split2(h0, h1, hi2, lo2);
            hh[b * 132 + jp] = hi2;
            hl[b * 132 + jp] = lo2;
        }
        __syncthreads();
    }

    // final: fused bf16 hi/lo conversion of hT for the output GEMM
    for (int i = tid; i < 8 * 128; i += 608) {
        int b = i / 128, kp = i - b * 128;
        int k0 = kp * 2;
        float v0 = (k0 < H_) ? shf[b * 200 + k0] : 0.f;
        float v1 = (k0 + 1 < H_) ? shf[b * 200 + k0 + 1] : 0.f;
        uint32_t hi2, lo2;
        pack_split2(v0, v1, hi2, lo2);
        *(uint32_t*)(g_h_hi + (size_t)(b0 + b) * KPAD + k0) = hi2;
        *(uint32_t*)(g_h_lo + (size_t)(b0 + b) * KPAD + k0) = lo2;
    }
}

// ---------------------------------------------------------------------------
// Wout conversion
// ---------------------------------------------------------------------------
__global__ void k_cvt_w(const float* __restrict__ Wout) {
    int nb = blockIdx.x * 256 + threadIdx.x;
    int k  = blockIdx.y;
    if (nb >= NPADW / 8) return;
    int n = nb * 8;

    union { unsigned short u[8]; uint4 v; } ph, pl;
    if (k < H_ && n + 7 < NITEMS) {
        const float4* src = (const float4*)(Wout + (size_t)k * NITEMS + n);
        float4 v0 = __ldg(src), v1 = __ldg(src + 1);
        float vv[8] = {v0.x, v0.y, v0.z, v0.w, v1.x, v1.y, v1.z, v1.w};
        #pragma unroll
        for (int j = 0; j < 8; ++j) bf_split(vv[j], ph.u[j], pl.u[j]);
    } else {
        #pragma unroll
        for (int j = 0; j < 8; ++j) {
            float v = (k < H_ && n + j < NITEMS) ? __ldg(Wout + (size_t)k * NITEMS + n + j) : 0.f;
            bf_split(v, ph.u[j], pl.u[j]);
        }
    }
    *(uint4*)(g_w_hi + (size_t)k * NPADW + n) = ph.v;
    *(uint4*)(g_w_lo + (size_t)k * NPADW + n) = pl.v;
}

// ---------------------------------------------------------------------------
// K4 mma.sync v3: 512 threads, BN=256, K=208 (chunks 64/64/64/16), cp.async.
// ---------------------------------------------------------------------------
#define OASTR 72
#define OBSTR 264
#define OUT_AB (128 * OASTR * 2)
#define OUT_BB (64 * OBSTR * 2)
#define OUT_BUF (2 * OUT_AB + 2 * OUT_BB)
#define MMA_SMEM (2 * OUT_BUF)              // 208896

__global__ void __launch_bounds__(512, 1)
k_out_mma(const float* __restrict__ bout, float* __restrict__ out) {
    extern __shared__ char smc[];
    const int tid  = threadIdx.x;
    const int wid  = tid >> 5, lane = tid & 31;
    const int mt   = blockIdx.x;
    const int nt   = blockIdx.y;
    const int wm   = wid & 1;
    const int wn   = wid >> 1;
    const uint32_t sbase = smem_u32(smc);

    auto fill = [&](int kc, int p) {
        const int nk = (kc < 3) ? 4 : 1;
        const int k0 = kc * 64;
        uint32_t buf = sbase + p * OUT_BUF;
        int per = nk * 2;
        int aTot = 2 * 128 * per;
        for (int i = tid; i < aTot; i += 512) {
            int split = i / (128 * per);
            int r = i - split * 128 * per;
            int m = r / per, kb = r - m * per;
            const __nv_bfloat16* src = (split ? g_h_lo : g_h_hi)
                + (size_t)(mt * 128 + m) * KPAD + k0 + kb * 8;
            cp16(buf + split * OUT_AB + (m * OASTR + kb * 8) * 2, src);
        }
        int rows = nk * 16;
        int bTot = 2 * rows * 32;
        for (int i = tid; i < bTot; i += 512) {
            int split = i / (rows * 32);
            int r = i - split * rows * 32;
            int k = r >> 5, nb = r & 31;
            const __nv_bfloat16* src = (split ? g_w_lo : g_w_hi)
                + (size_t)(k0 + k) * NPADW + nt * 256 + nb * 8;
            cp16(buf + 2 * OUT_AB + split * OUT_BB + (k * OBSTR + nb * 8) * 2, src);
        }
        asm volatile("cp.async.commit_group;" ::: "memory");
    };

    fill(0, 0);

    float acc[4][4][4];
    #pragma unroll
    for (int i = 0; i < 4; ++i)
        #pragma unroll
        for (int j = 0; j < 4; ++j)
            #pragma unroll
            for (int c = 0; c < 4; ++c) acc[i][j][c] = 0.f;

    for (int kc = 0; kc < 4; ++kc) {
        if (kc + 1 < 4) {
            fill(kc + 1, (kc + 1) & 1);
            asm volatile("cp.async.wait_group 1;" ::: "memory");
        } else {
            asm volatile("cp.async.wait_group 0;" ::: "memory");
        }
        __syncthreads();

        uint32_t buf = sbase + (kc & 1) * OUT_BUF;
        const uint32_t sAh32 = buf, sAl32 = buf + OUT_AB;
        const uint32_t sBh32 = buf + 2 * OUT_AB, sBl32 = sBh32 + OUT_BB;
        const int nk = (kc < 3) ? 4 : 1;

        #pragma unroll 4
        for (int ks = 0; ks < nk; ++ks) {
            uint32_t Ah[4][4], Al[4][4];
            #pragma unroll
            for (int fm = 0; fm < 4; ++fm) {
                uint32_t off = ((wm * 64 + fm * 16 + (lane & 15)) * OASTR
                                + ks * 16 + (lane >> 4) * 8) * 2;
                ldmA(Ah[fm], sAh32 + off);
                ldmA(Al[fm], sAl32 + off);
            }
            uint32_t Bh[4][2], Bl[4][2];
            #pragma unroll
            for (int fb = 0; fb < 2; ++fb) {
                uint32_t off = ((ks * 16 + (lane & 15)) * OBSTR
                                + wn * 32 + fb * 16 + (lane >> 4) * 8) * 2;
                uint32_t r[4];
                ldmBT(r, sBh32 + off);
                Bh[fb*2][0] = r[0]; Bh[fb*2][1] = r[1];
                Bh[fb*2+1][0] = r[2]; Bh[fb*2+1][1] = r[3];
                ldmBT(r, sBl32 + off);
                Bl[fb*2][0] = r[0]; Bl[fb*2][1] = r[1];
                Bl[fb*2+1][0] = r[2]; Bl[fb*2+1][1] = r[3];
            }
            #pragma unroll
            for (int fm = 0; fm < 4; ++fm)
                #pragma unroll
                for (int fn = 0; fn < 4; ++fn) {
                    mma_bf16(acc[fm][fn], Ah[fm], Bh[fn]);
                    mma_bf16(acc[fm][fn], Ah[fm], Bl[fn]);
                    mma_bf16(acc[fm][fn], Al[fm], Bh[fn]);
                }
        }
        __syncthreads();
    }

    #pragma unroll
    for (int fm = 0; fm < 4; ++fm) {
        int gm = mt * 128 + wm * 64 + fm * 16 + (lane >> 2);
        #pragma unroll
        for (int fn = 0; fn < 4; ++fn) {
            int gn = nt * 256 + wn * 32 + fn * 8 + (lane & 3) * 2;
            if (gn < NITEMS) {
                float2 bv = __ldg((const float2*)(bout + gn));
                float2 o0 = make_float2(acc[fm][fn][0] + bv.x, acc[fm][fn][1] + bv.y);
                float2 o1 = make_float2(acc[fm][fn][2] + bv.x, acc[fm][fn][3] + bv.y);
                *(float2*)(out + (size_t)gm * NITEMS + gn) = o0;
                *(float2*)(out + (size_t)(gm + 8) * NITEMS + gn) = o1;
            }
        }
    }
}

// ---------------------------------------------------------------------------
extern "C" void kernel_launch(void* const* d_in, const int* in_sizes, int n_in,
                              void* d_out, int out_size) {
    const int*   q    = (const int*)  d_in[0];
    const int*   f    = (const int*)  d_in[1];
    const float* eq   = (const float*)d_in[2];
    const float* ef   = (const float*)d_in[3];
    const float* ic   = (const float*)d_in[4];
    const float* Wi   = (const float*)d_in[5];
    const float* bi   = (const float*)d_in[6];
    const float* Wh   = (const float*)d_in[7];
    const float* bhn  = (const float*)d_in[8];
    const float* Wout = (const float*)d_in[9];
    const float* bout = (const float*)d_in[10];
    float* out = (float*)d_out;

    static bool attr_done = false;
    if (!attr_done) {
        cudaFuncSetAttribute(k_gi_mma,   cudaFuncAttributeMaxDynamicSharedMemorySize, GI3_SMEM);
        cudaFuncSetAttribute(k_scan_mma, cudaFuncAttributeMaxDynamicSharedMemorySize, SCAN_SMEM);
        cudaFuncSetAttribute(k_out_mma,  cudaFuncAttributeMaxDynamicSharedMemorySize, MMA_SMEM);
        attr_done = true;
    }

    // Wout -> bf16 hi/lo
    {
        dim3 grid((NPADW / 8 + 255) / 256, KPAD);
        k_cvt_w<<<grid, 256>>>(Wout);
    }
    // Wi -> linear bf16 hi/lo
    k_cvt_wi<<<(T_ * GI_KP * 80 + 255) / 256, 256>>>(Wi);
    // Wh -> fragment bf16 hi/lo (38 mtiles used)
    {
        dim3 grid(38, 200);
        k_cvt_whf<<<grid, 128>>>(Wh);
    }
    // GI = (gathered state) @ Wi + bi
    {
        dim3 grid(8, 200);
        k_gi_mma<<<grid, 512, GI3_SMEM>>>(q, f, eq, ef, bi);
    }
    // GRU scan (tensor cores)
    k_scan_mma<<<128, 608, SCAN_SMEM>>>(bhn, ic);
    // out = hT @ Wout + bout (tensor cores, 16 warps, K=208, BN=256)
    {
        dim3 grid(8, NT3);
        k_out_mma<<<grid, 512, MMA_SMEM>>>(bout, out);
    }
}

// round 17
// speedup vs baseline: 1.0379x; 1.0126x over previous
#include <cuda_runtime.h>
#include <cuda_bf16.h>
#include <cstdint>

// Problem constants
#define B_   1024
#define T_   200
#define E_   100
#define H_   200
#define G3_  600      // 3*H
#define NITEMS 100000

#define KPAD 256             // K padded storage for output GEMM operands
#define NT3  391             // ceil(100000/256)
#define NPADW (NT3*256)      // 100096

#define GI_KP 112            // K pad for GI GEMM
#define GI_NP 640            // N pad for GI GEMM

// Scratch (device globals; allocation is forbidden)
__device__ float g_GI[(size_t)T_ * B_ * G3_]; // gi = x@Wi+bi  [t][b][600]

// bf16 hi/lo operands for the mma.sync output GEMM
__device__ __nv_bfloat16 g_w_hi[(size_t)KPAD * NPADW];  // [k][n]
__device__ __nv_bfloat16 g_w_lo[(size_t)KPAD * NPADW];
__device__ __nv_bfloat16 g_h_hi[B_ * KPAD];             // [m][k]
__device__ __nv_bfloat16 g_h_lo[B_ * KPAD];
// Wh pre-fragged for scan mma: [t][mt 40][ks 13][lane 32] uint4
__device__ uint4 g_whf_hi[(size_t)T_ * 40 * 13 * 32];
__device__ uint4 g_whf_lo[(size_t)T_ * 40 * 13 * 32];
// Wi linear bf16 hi/lo for GI GEMM: [t][112][640]
__device__ __nv_bfloat16 g_wi_hi[(size_t)T_ * GI_KP * GI_NP];
__device__ __nv_bfloat16 g_wi_lo[(size_t)T_ * GI_KP * GI_NP];

static __device__ __forceinline__ float tanh_fast(float x) {
    float y; asm("tanh.approx.f32 %0, %1;" : "=f"(y) : "f"(x)); return y;
}
static __device__ __forceinline__ float sig_fast(float x) {
    return fmaf(tanh_fast(0.5f * x), 0.5f, 0.5f);
}
static __device__ __forceinline__ uint32_t smem_u32(const void* p) {
    uint32_t a;
    asm("{ .reg .u64 t; cvta.to.shared.u64 t, %1; cvt.u32.u64 %0, t; }" : "=r"(a) : "l"(p));
    return a;
}

// ---------------- mma.sync helpers ----------------
static __device__ __forceinline__ void ldmA(uint32_t* r, uint32_t addr) {
    asm volatile("ldmatrix.sync.aligned.m8n8.x4.shared.b16 {%0,%1,%2,%3}, [%4];"
        : "=r"(r[0]), "=r"(r[1]), "=r"(r[2]), "=r"(r[3]) : "r"(addr));
}
static __device__ __forceinline__ void ldmBT(uint32_t* r, uint32_t addr) {
    asm volatile("ldmatrix.sync.aligned.m8n8.x4.trans.shared.b16 {%0,%1,%2,%3}, [%4];"
        : "=r"(r[0]), "=r"(r[1]), "=r"(r[2]), "=r"(r[3]) : "r"(addr));
}
static __device__ __forceinline__ void mma_bf16(float* c, const uint32_t* a, const uint32_t* b) {
    asm volatile("mma.sync.aligned.m16n8k16.row.col.f32.bf16.bf16.f32 "
        "{%0,%1,%2,%3}, {%4,%5,%6,%7}, {%8,%9}, {%0,%1,%2,%3};"
        : "+f"(c[0]), "+f"(c[1]), "+f"(c[2]), "+f"(c[3])
        : "r"(a[0]), "r"(a[1]), "r"(a[2]), "r"(a[3]), "r"(b[0]), "r"(b[1]));
}
static __device__ __forceinline__ void bf_split(float v, unsigned short& h, unsigned short& l) {
    __nv_bfloat16 hh = __float2bfloat16(v);
    h = __bfloat16_as_ushort(hh);
    l = __bfloat16_as_ushort(__float2bfloat16(v - __bfloat162float(hh)));
}
static __device__ __forceinline__ void pack_split2(float v0, float v1, uint32_t& hi2, uint32_t& lo2) {
    asm("cvt.rn.bf16x2.f32 %0, %1, %2;" : "=r"(hi2) : "f"(v1), "f"(v0));
    float h0 = __uint_as_float(hi2 << 16);
    float h1 = __uint_as_float((hi2 >> 16) << 16);
    asm("cvt.rn.bf16x2.f32 %0, %1, %2;" : "=r"(lo2) : "f"(v1 - h1), "f"(v0 - h0));
}
static __device__ __forceinline__ void cp16(uint32_t dst, const void* src) {
    asm volatile("cp.async.cg.shared.global [%0], [%1], 16;" :: "r"(dst), "l"(src) : "memory");
}

// ---------------------------------------------------------------------------
// Wi conversion: [200][100][600] fp32 -> linear [200][112][640] bf16 hi/lo
// ---------------------------------------------------------------------------
__global__ void k_cvt_wi(const float* __restrict__ Wi) {
    int idx = blockIdx.x * 256 + threadIdx.x;   // 200*112*80
    if (idx >= T_ * GI_KP * 80) return;
    int n8 = idx % 80;
    int k  = (idx / 80) % GI_KP;
    int t  = idx / (80 * GI_KP);
    int n  = n8 * 8;

    union { unsigned short u[8]; uint4 v; } ph, pl;
    #pragma unroll
    for (int j = 0; j < 8; ++j) {
        float v = (k < E_ && n + j < G3_) ? __ldg(Wi + ((size_t)t * E_ + k) * G3_ + n + j) : 0.f;
        bf_split(v, ph.u[j], pl.u[j]);
    }
    size_t dst = ((size_t)t * GI_KP + k) * GI_NP + n;
    *(uint4*)(g_wi_hi + dst) = ph.v;
    *(uint4*)(g_wi_lo + dst) = pl.v;
}

// ---------------------------------------------------------------------------
// K2 mma v4: grid (bt 8, t 200); per CTA M=128 x N=640 x K=112.
// 256 threads (8 warps: 2m x 4n), B chunks of 64 cols (10 chunks),
// SINGLE-buffered, 2 CTAs/SM for cross-CTA overlap. smem 93696 B.
// ---------------------------------------------------------------------------
#define GIA_STR 120
#define GIB_STR 72
#define GI4_A_BYTES (128 * GIA_STR * 2)                 // 30720 per split
#define GI4_B_SPLIT (GI_KP * GIB_STR * 2)               // 16128
#define GI4_SMEM    (2 * GI4_A_BYTES + 2 * GI4_B_SPLIT) // 93696

__global__ void __launch_bounds__(256, 2)
k_gi_mma(const int* __restrict__ q, const int* __restrict__ f,
         const float* __restrict__ eq, const float* __restrict__ ef,
         const float* __restrict__ bi) {
    extern __shared__ char sm[];
    __nv_bfloat16* sAh = (__nv_bfloat16*)sm;                      // [128][120]
    __nv_bfloat16* sAl = (__nv_bfloat16*)(sm + GI4_A_BYTES);
    char* sB = sm + 2 * GI4_A_BYTES;                              // [2][112][72]
    __shared__ int sq[128], sf[128];
    __shared__ float sbi[608];

    const int tid  = threadIdx.x;
    const int wid  = tid >> 5, lane = tid & 31;
    const int bt   = blockIdx.x;       // 0..7
    const int t    = blockIdx.y;       // 0..199
    const int wm   = wid & 1;          // m half (64)
    const int wn   = wid >> 1;         // 0..3 : 16-col group within 64 chunk
    const int b_base = bt * 128;

    const uint32_t sB32 = smem_u32(sB);
    // B chunk fill via cp.async (single buffer): 2 splits x 112 k x 8 j = 1792
    auto fillB = [&](int c) {
        size_t srcbase = (size_t)t * GI_KP * GI_NP + c * 64;
        for (int i = tid; i < 1792; i += 256) {
            int split = i / 896;
            int r = i - split * 896;
            int k = r >> 3, j = r & 7;
            const __nv_bfloat16* src = (split ? g_wi_lo : g_wi_hi) + srcbase + (size_t)k * GI_NP + j * 8;
            uint32_t dst = sB32 + split * GI4_B_SPLIT + (k * GIB_STR + j * 8) * 2;
            cp16(dst, src);
        }
        asm volatile("cp.async.commit_group;" ::: "memory");
    };

    fillB(0);

    if (tid < 128) {
        sq[tid] = __ldg(q + (b_base + tid) * T_ + t);
        sf[tid] = __ldg(f + (b_base + tid) * T_ + t);
    }
    for (int i = tid; i < G3_; i += 256)
        sbi[i] = __ldg(bi + t * G3_ + i);
    __syncthreads();

    // A fill: gather+product -> bf16 hi/lo, [m][k] stride 120
    for (int i = tid; i < 128 * 25; i += 256) {
        int m = i / 25, c4 = i - m * 25;
        int k0 = c4 * 4;
        float4 a = __ldg((const float4*)(eq + sq[m] * E_ + k0));
        float4 b = __ldg((const float4*)(ef + sf[m] * E_ + k0));
        float vv[4] = {a.x * b.x, a.y * b.y, a.z * b.z, a.w * b.w};
        union { unsigned short u[4]; uint2 v; } ph, pl;
        #pragma unroll
        for (int j = 0; j < 4; ++j) bf_split(vv[j], ph.u[j], pl.u[j]);
        *(uint2*)(sAh + m * GIA_STR + k0) = ph.v;
        *(uint2*)(sAl + m * GIA_STR + k0) = pl.v;
    }
    for (int i = tid; i < 128 * 6; i += 256) {
        int m = i / 6, kk = 100 + 2 * (i - m * 6);
        *(uint32_t*)(sAh + m * GIA_STR + kk) = 0;
        *(uint32_t*)(sAl + m * GIA_STR + kk) = 0;
    }

    const uint32_t sAh32 = smem_u32(sAh), sAl32 = smem_u32(sAl);
    const uint32_t bh32 = sB32, bl32 = sB32 + GI4_B_SPLIT;

    for (int c = 0; c < 10; ++c) {
        asm volatile("cp.async.wait_group 0;" ::: "memory");
        __syncthreads();

        float acc[4][2][4];
        #pragma unroll
        for (int i = 0; i < 4; ++i)
            #pragma unroll
            for (int j = 0; j < 2; ++j)
                #pragma unroll
                for (int k = 0; k < 4; ++k) acc[i][j][k] = 0.f;

        #pragma unroll
        for (int ks = 0; ks < 7; ++ks) {
            uint32_t Ah[4][4], Al[4][4];
            #pragma unroll
            for (int fm = 0; fm < 4; ++fm) {
                uint32_t off = ((wm * 64 + fm * 16 + (lane & 15)) * GIA_STR
                                + ks * 16 + (lane >> 4) * 8) * 2;
                ldmA(Ah[fm], sAh32 + off);
                ldmA(Al[fm], sAl32 + off);
            }
            uint32_t Bh[2][2], Bl[2][2];
            {
                uint32_t off = ((ks * 16 + (lane & 15)) * GIB_STR
                                + wn * 16 + (lane >> 4) * 8) * 2;
                uint32_t r[4];
                ldmBT(r, bh32 + off);
                Bh[0][0] = r[0]; Bh[0][1] = r[1];
                Bh[1][0] = r[2]; Bh[1][1] = r[3];
                ldmBT(r, bl32 + off);
                Bl[0][0] = r[0]; Bl[0][1] = r[1];
                Bl[1][0] = r[2]; Bl[1][1] = r[3];
            }
            #pragma unroll
            for (int fm = 0; fm < 4; ++fm)
                #pragma unroll
                for (int fn = 0; fn < 2; ++fn) {
                    mma_bf16(acc[fm][fn], Ah[fm], Bh[fn]);
                    mma_bf16(acc[fm][fn], Ah[fm], Bl[fn]);
                    mma_bf16(acc[fm][fn], Al[fm], Bh[fn]);
                }
        }
        __syncthreads();           // B reads complete before refill
        if (c + 1 < 10) fillB(c + 1);

        #pragma unroll
        for (int fm = 0; fm < 4; ++fm) {
            int gm = b_base + wm * 64 + fm * 16 + (lane >> 2);
            #pragma unroll
            for (int fn = 0; fn < 2; ++fn) {
                int gn = c * 64 + wn * 16 + fn * 8 + (lane & 3) * 2;
                if (gn < G3_) {
                    float2 bv = *(float2*)&sbi[gn];
                    float2 o0 = make_float2(acc[fm][fn][0] + bv.x, acc[fm][fn][1] + bv.y);
                    float2 o1 = make_float2(acc[fm][fn][2] + bv.x, acc[fm][fn][3] + bv.y);
                    *(float2*)(g_GI + ((size_t)t * B_ + gm) * G3_ + gn) = o0;
                    *(float2*)(g_GI + ((size_t)t * B_ + gm + 8) * G3_ + gn) = o1;
                }
            }
        }
    }
}

// ---------------------------------------------------------------------------
// Wh -> fragment layout conversion (once).
// ---------------------------------------------------------------------------
__global__ void __launch_bounds__(128)
k_cvt_whf(const float* __restrict__ Wh) {
    __shared__ float sA[208][17];
    const int mt = blockIdx.x;   // 0..37
    const int t  = blockIdx.y;
    const int tid = threadIdx.x;
    const int m0 = mt * 16;

    for (int i = tid; i < 208 * 16; i += 128) {
        int k = i >> 4, mm = i & 15;
        int m = m0 + mm;
        float v = (k < H_ && m < G3_) ? __ldg(Wh + ((size_t)t * H_ + k) * G3_ + m) : 0.f;
        sA[k][mm] = v;
    }
    __syncthreads();

    const int wid = tid >> 5, lane = tid & 31;
    const int g = lane >> 2, c = lane & 3;
    for (int ks = wid; ks < 13; ks += 4) {
        int k0 = ks * 16 + 2 * c;
        uint4 uh, ul;
        pack_split2(sA[k0][g],       sA[k0 + 1][g],     uh.x, ul.x);
        pack_split2(sA[k0][g + 8],   sA[k0 + 1][g + 8], uh.y, ul.y);
        pack_split2(sA[k0 + 8][g],   sA[k0 + 9][g],     uh.z, ul.z);
        pack_split2(sA[k0 + 8][g+8], sA[k0 + 9][g + 8], uh.w, ul.w);
        size_t idx = (((size_t)t * 40 + mt) * 13 + ks) * 32 + lane;
        g_whf_hi[idx] = uh;
        g_whf_lo[idx] = ul;
    }
}

// ---------------------------------------------------------------------------
// K3: GRU scan v9. 128 CTAs x 8 rows, 608 threads.
// ---------------------------------------------------------------------------
#define SOFF_GI   0                      // [8][600] f32    19200
#define SOFF_GH   19200                  // [608][10] f32   24320
#define SOFF_HF   43520                  // [8][200] f32    6400
#define SOFF_HHI  49920                  // [8][132] u32    4224
#define SOFF_HLO  54144                  //                 4224
#define SOFF_BHN  58368                  // [200] f32       800
#define SCAN_SMEM 59168

#define WHF_S1    (19 * 13 * 32)
#define WHF_TSTEP (40 * 13 * 32)

__global__ void __launch_bounds__(608, 1)
k_scan_mma(const float* __restrict__ bhn, const float* __restrict__ ic) {
    extern __shared__ char sm[];
    float*    sgi = (float*)(sm + SOFF_GI);
    float*    sgh = (float*)(sm + SOFF_GH);
    float*    shf = (float*)(sm + SOFF_HF);
    uint32_t* hh  = (uint32_t*)(sm + SOFF_HHI);
    uint32_t* hl  = (uint32_t*)(sm + SOFF_HLO);
    float*    sbh = (float*)(sm + SOFF_BHN);

    const int tid  = threadIdx.x;
    const int wid  = tid >> 5, lane = tid & 31;
    const int b0   = blockIdx.x * 8;
    const int g    = lane >> 2, cc = lane & 3;
    const uint32_t sgi_a = smem_u32(sgi);
    const uint32_t sbh_a = smem_u32(sbh);

    for (int i = tid; i < 8 * 132; i += 608) {
        int w = i % 132;
        uint32_t hi2 = 0, lo2 = 0;
        if (w < 100) {
            float v0 = __ldg(ic + 2 * w), v1 = __ldg(ic + 2 * w + 1);
            pack_split2(v0, v1, hi2, lo2);
        }
        hh[i] = hi2; hl[i] = lo2;
    }
    for (int i = tid; i < 1600; i += 608)
        shf[i] = __ldg(ic + (i % 200));
    __syncthreads();

    float acc0a[4], acc0b[4], acc1a[4], acc1b[4];
    uint4 bh0[2], bl0[2], bh1[2], bl1[2];

    const uint4* ph = g_whf_hi + ((size_t)wid * 13) * 32 + lane;
    const uint4* pl = g_whf_lo + ((size_t)wid * 13) * 32 + lane;

    bh0[0] = __ldg(ph);               bl0[0] = __ldg(pl);
    bh1[0] = __ldg(ph + WHF_S1);      bl1[0] = __ldg(pl + WHF_S1);
    bh0[1] = __ldg(ph + 32);          bl0[1] = __ldg(pl + 32);
    bh1[1] = __ldg(ph + WHF_S1 + 32); bl1[1] = __ldg(pl + WHF_S1 + 32);

    for (int t = 0; t < T_; ++t) {
        {
            const float* gib = g_GI + ((size_t)t * B_ + b0) * G3_;
            for (int i = tid; i < 1250; i += 608) {
                if (i < 1200) {
                    int b = i / 150, o = (i - b * 150) * 16;
                    cp16(sgi_a + b * 2400 + o, (const char*)(gib + b * G3_) + o);
                } else {
                    int j = i - 1200;
                    cp16(sbh_a + j * 16, (const char*)(bhn + t * H_) + j * 16);
                }
            }
            asm volatile("cp.async.commit_group;" ::: "memory");
        }

        #pragma unroll
        for (int c = 0; c < 4; ++c) { acc0a[c] = 0.f; acc0b[c] = 0.f; acc1a[c] = 0.f; acc1b[c] = 0.f; }

        #pragma unroll
        for (int ks = 0; ks < 13; ++ks) {
            const int p = ks & 1;
            uint4 a0h = bh0[p], a0l = bl0[p], a1h = bh1[p], a1l = bl1[p];
            if (ks + 2 < 13) {
                int off = (ks + 2) * 32;
                bh0[p] = __ldg(ph + off);          bl0[p] = __ldg(pl + off);
                bh1[p] = __ldg(ph + WHF_S1 + off); bl1[p] = __ldg(pl + WHF_S1 + off);
            }
            int r0 = g * 132 + ks * 8 + cc;
            uint32_t Bh[2] = { hh[r0], hh[r0 + 4] };
            uint32_t Bl[2] = { hl[r0], hl[r0 + 4] };
            uint32_t Ah0[4] = {a0h.x, a0h.y, a0h.z, a0h.w};
            uint32_t Al0[4] = {a0l.x, a0l.y, a0l.z, a0l.w};
            uint32_t Ah1[4] = {a1h.x, a1h.y, a1h.z, a1h.w};
            uint32_t Al1[4] = {a1l.x, a1l.y, a1l.z, a1l.w};
            mma_bf16(acc0a, Ah0, Bh);
            mma_bf16(acc1a, Ah1, Bh);
            mma_bf16(acc0b, Ah0, Bl);
            mma_bf16(acc1b, Ah1, Bl);
            mma_bf16(acc0b, Al0, Bh);
            mma_bf16(acc1b, Al1, Bh);
        }

        {
            int m0 = wid * 16;
            *(float2*)&sgh[(m0 + g) * 10 + cc * 2]     = make_float2(acc0a[0] + acc0b[0], acc0a[1] + acc0b[1]);
            *(float2*)&sgh[(m0 + g + 8) * 10 + cc * 2] = make_float2(acc0a[2] + acc0b[2], acc0a[3] + acc0b[3]);
            int m1 = (wid + 19) * 16;
            *(float2*)&sgh[(m1 + g) * 10 + cc * 2]     = make_float2(acc1a[0] + acc1b[0], acc1a[1] + acc1b[1]);
            *(float2*)&sgh[(m1 + g + 8) * 10 + cc * 2] = make_float2(acc1a[2] + acc1b[2], acc1a[3] + acc1b[3]);
        }

        if (t + 1 < T_) {
            ph += WHF_TSTEP;
            pl += WHF_TSTEP;
            bh0[0] = __ldg(ph);               bl0[0] = __ldg(pl);
            bh1[0] = __ldg(ph + WHF_S1);      bl1[0] = __ldg(pl + WHF_S1);
            bh0[1] = __ldg(ph + 32);          bl0[1] = __ldg(pl + 32);
            bh1[1] = __ldg(ph + WHF_S1 + 32); bl1[1] = __ldg(pl + WHF_S1 + 32);
        }

        asm volatile("cp.async.wait_group 0;" ::: "memory");
        __syncthreads();

        for (int i = tid; i < 800; i += 608) {
            int b = i / 100, jp = i - b * 100, j = jp * 2;
            const float* gib = sgi + b * G3_;
            float2 gr = *(const float2*)(gib + j);
            float2 gz = *(const float2*)(gib + 200 + j);
            float2 gn = *(const float2*)(gib + 400 + j);
            float ghr0 = sgh[j * 10 + b],         ghr1 = sgh[(j + 1) * 10 + b];
            float ghz0 = sgh[(200 + j) * 10 + b], ghz1 = sgh[(201 + j) * 10 + b];
            float ghn0 = sgh[(400 + j) * 10 + b], ghn1 = sgh[(401 + j) * 10 + b];
            float2 bv = *(const float2*)(sbh + j);
            float2 ho = *(const float2*)(shf + b * 200 + j);
            float r0 = sig_fast(gr.x + ghr0), r1 = sig_fast(gr.y + ghr1);
            float z0 = sig_fast(gz.x + ghz0), z1 = sig_fast(gz.y + ghz1);
            float n0 = tanh_fast(gn.x + r0 * (ghn0 + bv.x));
            float n1 = tanh_fast(gn.y + r1 * (ghn1 + bv.y));
            float h0 = (1.f - z0) * n0 + z0 * ho.x;
            float h1 = (1.f - z1) * n1 + z1 * ho.y;
            *(float2*)(shf + b * 200 + j) = make_float2(h0, h1);
            uint32_t hi2, lo2;
            pack_split2(h0, h1, hi2, lo2);
            hh[b * 132 + jp] = hi2;
            hl[b * 132 + jp] = lo2;
        }
        __syncthreads();
    }

    // final: fused bf16 hi/lo conversion of hT for the output GEMM
    for (int i = tid; i < 8 * 128; i += 608) {
        int b = i / 128, kp = i - b * 128;
        int k0 = kp * 2;
        float v0 = (k0 < H_) ? shf[b * 200 + k0] : 0.f;
        float v1 = (k0 + 1 < H_) ? shf[b * 200 + k0 + 1] : 0.f;
        uint32_t hi2, lo2;
        pack_split2(v0, v1, hi2, lo2);
        *(uint32_t*)(g_h_hi + (size_t)(b0 + b) * KPAD + k0) = hi2;
        *(uint32_t*)(g_h_lo + (size_t)(b0 + b) * KPAD + k0) = lo2;
    }
}

// ---------------------------------------------------------------------------
// Wout conversion
// ---------------------------------------------------------------------------
__global__ void k_cvt_w(const float* __restrict__ Wout) {
    int nb = blockIdx.x * 256 + threadIdx.x;
    int k  = blockIdx.y;
    if (nb >= NPADW / 8) return;
    int n = nb * 8;

    union { unsigned short u[8]; uint4 v; } ph, pl;
    if (k < H_ && n + 7 < NITEMS) {
        const float4* src = (const float4*)(Wout + (size_t)k * NITEMS + n);
        float4 v0 = __ldg(src), v1 = __ldg(src + 1);
        float vv[8] = {v0.x, v0.y, v0.z, v0.w, v1.x, v1.y, v1.z, v1.w};
        #pragma unroll
        for (int j = 0; j < 8; ++j) bf_split(vv[j], ph.u[j], pl.u[j]);
    } else {
        #pragma unroll
        for (int j = 0; j < 8; ++j) {
            float v = (k < H_ && n + j < NITEMS) ? __ldg(Wout + (size_t)k * NITEMS + n + j) : 0.f;
            bf_split(v, ph.u[j], pl.u[j]);
        }
    }
    *(uint4*)(g_w_hi + (size_t)k * NPADW + n) = ph.v;
    *(uint4*)(g_w_lo + (size_t)k * NPADW + n) = pl.v;
}

// ---------------------------------------------------------------------------
// K4 mma.sync v3: 512 threads, BN=256, K=208 (chunks 64/64/64/16), cp.async.
// ---------------------------------------------------------------------------
#define OASTR 72
#define OBSTR 264
#define OUT_AB (128 * OASTR * 2)
#define OUT_BB (64 * OBSTR * 2)
#define OUT_BUF (2 * OUT_AB + 2 * OUT_BB)
#define MMA_SMEM (2 * OUT_BUF)              // 208896

__global__ void __launch_bounds__(512, 1)
k_out_mma(const float* __restrict__ bout, float* __restrict__ out) {
    extern __shared__ char smc[];
    const int tid  = threadIdx.x;
    const int wid  = tid >> 5, lane = tid & 31;
    const int mt   = blockIdx.x;
    const int nt   = blockIdx.y;
    const int wm   = wid & 1;
    const int wn   = wid >> 1;
    const uint32_t sbase = smem_u32(smc);

    auto fill = [&](int kc, int p) {
        const int nk = (kc < 3) ? 4 : 1;
        const int k0 = kc * 64;
        uint32_t buf = sbase + p * OUT_BUF;
        int per = nk * 2;
        int aTot = 2 * 128 * per;
        for (int i = tid; i < aTot; i += 512) {
            int split = i / (128 * per);
            int r = i - split * 128 * per;
            int m = r / per, kb = r - m * per;
            const __nv_bfloat16* src = (split ? g_h_lo : g_h_hi)
                + (size_t)(mt * 128 + m) * KPAD + k0 + kb * 8;
            cp16(buf + split * OUT_AB + (m * OASTR + kb * 8) * 2, src);
        }
        int rows = nk * 16;
        int bTot = 2 * rows * 32;
        for (int i = tid; i < bTot; i += 512) {
            int split = i / (rows * 32);
            int r = i - split * rows * 32;
            int k = r >> 5, nb = r & 31;
            const __nv_bfloat16* src = (split ? g_w_lo : g_w_hi)
                + (size_t)(k0 + k) * NPADW + nt * 256 + nb * 8;
            cp16(buf + 2 * OUT_AB + split * OUT_BB + (k * OBSTR + nb * 8) * 2, src);
        }
        asm volatile("cp.async.commit_group;" ::: "memory");
    };

    fill(0, 0);

    float acc[4][4][4];
    #pragma unroll
    for (int i = 0; i < 4; ++i)
        #pragma unroll
        for (int j = 0; j < 4; ++j)
            #pragma unroll
            for (int c = 0; c < 4; ++c) acc[i][j][c] = 0.f;

    for (int kc = 0; kc < 4; ++kc) {
        if (kc + 1 < 4) {
            fill(kc + 1, (kc + 1) & 1);
            asm volatile("cp.async.wait_group 1;" ::: "memory");
        } else {
            asm volatile("cp.async.wait_group 0;" ::: "memory");
        }
        __syncthreads();

        uint32_t buf = sbase + (kc & 1) * OUT_BUF;
        const uint32_t sAh32 = buf, sAl32 = buf + OUT_AB;
        const uint32_t sBh32 = buf + 2 * OUT_AB, sBl32 = sBh32 + OUT_BB;
        const int nk = (kc < 3) ? 4 : 1;

        #pragma unroll 4
        for (int ks = 0; ks < nk; ++ks) {
            uint32_t Ah[4][4], Al[4][4];
            #pragma unroll
            for (int fm = 0; fm < 4; ++fm) {
                uint32_t off = ((wm * 64 + fm * 16 + (lane & 15)) * OASTR
                                + ks * 16 + (lane >> 4) * 8) * 2;
                ldmA(Ah[fm], sAh32 + off);
                ldmA(Al[fm], sAl32 + off);
            }
            uint32_t Bh[4][2], Bl[4][2];
            #pragma unroll
            for (int fb = 0; fb < 2; ++fb) {
                uint32_t off = ((ks * 16 + (lane & 15)) * OBSTR
                                + wn * 32 + fb * 16 + (lane >> 4) * 8) * 2;
                uint32_t r[4];
                ldmBT(r, sBh32 + off);
                Bh[fb*2][0] = r[0]; Bh[fb*2][1] = r[1];
                Bh[fb*2+1][0] = r[2]; Bh[fb*2+1][1] = r[3];
                ldmBT(r, sBl32 + off);
                Bl[fb*2][0] = r[0]; Bl[fb*2][1] = r[1];
                Bl[fb*2+1][0] = r[2]; Bl[fb*2+1][1] = r[3];
            }
            #pragma unroll
            for (int fm = 0; fm < 4; ++fm)
                #pragma unroll
                for (int fn = 0; fn < 4; ++fn) {
                    mma_bf16(acc[fm][fn], Ah[fm], Bh[fn]);
                    mma_bf16(acc[fm][fn], Ah[fm], Bl[fn]);
                    mma_bf16(acc[fm][fn], Al[fm], Bh[fn]);
                }
        }
        __syncthreads();
    }

    #pragma unroll
    for (int fm = 0; fm < 4; ++fm) {
        int gm = mt * 128 + wm * 64 + fm * 16 + (lane >> 2);
        #pragma unroll
        for (int fn = 0; fn < 4; ++fn) {
            int gn = nt * 256 + wn * 32 + fn * 8 + (lane & 3) * 2;
            if (gn < NITEMS) {
                float2 bv = __ldg((const float2*)(bout + gn));
                float2 o0 = make_float2(acc[fm][fn][0] + bv.x, acc[fm][fn][1] + bv.y);
                float2 o1 = make_float2(acc[fm][fn][2] + bv.x, acc[fm][fn][3] + bv.y);
                *(float2*)(out + (size_t)gm * NITEMS + gn) = o0;
                *(float2*)(out + (size_t)(gm + 8) * NITEMS + gn) = o1;
            }
        }
    }
}

// ---------------------------------------------------------------------------
extern "C" void kernel_launch(void* const* d_in, const int* in_sizes, int n_in,
                              void* d_out, int out_size) {
    const int*   q    = (const int*)  d_in[0];
    const int*   f    = (const int*)  d_in[1];
    const float* eq   = (const float*)d_in[2];
    const float* ef   = (const float*)d_in[3];
    const float* ic   = (const float*)d_in[4];
    const float* Wi   = (const float*)d_in[5];
    const float* bi   = (const float*)d_in[6];
    const float* Wh   = (const float*)d_in[7];
    const float* bhn  = (const float*)d_in[8];
    const float* Wout = (const float*)d_in[9];
    const float* bout = (const float*)d_in[10];
    float* out = (float*)d_out;

    static bool attr_done = false;
    if (!attr_done) {
        cudaFuncSetAttribute(k_gi_mma,   cudaFuncAttributeMaxDynamicSharedMemorySize, GI4_SMEM);
        cudaFuncSetAttribute(k_scan_mma, cudaFuncAttributeMaxDynamicSharedMemorySize, SCAN_SMEM);
        cudaFuncSetAttribute(k_out_mma,  cudaFuncAttributeMaxDynamicSharedMemorySize, MMA_SMEM);
        attr_done = true;
    }

    // Wout -> bf16 hi/lo
    {
        dim3 grid((NPADW / 8 + 255) / 256, KPAD);
        k_cvt_w<<<grid, 256>>>(Wout);
    }
    // Wi -> linear bf16 hi/lo
    k_cvt_wi<<<(T_ * GI_KP * 80 + 255) / 256, 256>>>(Wi);
    // Wh -> fragment bf16 hi/lo
    {
        dim3 grid(38, 200);
        k_cvt_whf<<<grid, 128>>>(Wh);
    }
    // GI = (gathered state) @ Wi + bi (256 thr, 2 CTAs/SM)
    {
        dim3 grid(8, 200);
        k_gi_mma<<<grid, 256, GI4_SMEM>>>(q, f, eq, ef, bi);
    }
    // GRU scan (tensor cores)
    k_scan_mma<<<128, 608, SCAN_SMEM>>>(bhn, ic);
    // out = hT @ Wout + bout (tensor cores)
    {
        dim3 grid(8, NT3);
        k_out_mma<<<grid, 512, MMA_SMEM>>>(bout, out);
    }
}